// round 13
// baseline (speedup 1.0000x reference)
#include <cuda_runtime.h>
#include <cuda_bf16.h>
#include <cstdint>
#include <math.h>

typedef unsigned int u32;

#define B_  32
#define M_  64
#define Kk_ 36
#define DS_ 512
#define DX_ 128
#define DQ_ 512
#define H_  256
#define ROWS_S 2048
#define ROWS_X 1152

// Scratch (allocation-free rule: __device__ globals)
__device__ __align__(16) float g_preq[B_*H_];
__device__ __align__(16) float g_C[ROWS_S*512];      // 0:256 pre_s (raw), 256:512 h1=relu(..+hb1)
__device__ __align__(16) float g_hs[ROWS_S*DX_];
__device__ __align__(16) float g_base[ROWS_X*H_];
__device__ __align__(16) __nv_bfloat16 g_Ahi[ROWS_S*512];
__device__ __align__(16) __nv_bfloat16 g_Alo[ROWS_S*512];
__device__ __align__(16) __nv_bfloat16 g_Whi[512*512];  // cols 0:256 w_s, 256:512 hw1
__device__ __align__(16) __nv_bfloat16 g_Wlo[512*512];

__device__ __forceinline__ void fma2(float2 &d, const float2 &a, const float2 &b) {
    asm("fma.rn.f32x2 %0, %1, %2, %0;"
        : "+l"(reinterpret_cast<unsigned long long&>(d))
        : "l"(reinterpret_cast<const unsigned long long&>(a)),
          "l"(reinterpret_cast<const unsigned long long&>(b)));
}

__device__ __forceinline__ u32 smem_addr_u32(const void* zp) {
    return (u32)__cvta_generic_to_shared(zp);
}
__device__ __forceinline__ void ld_sm_x4(u32* zr, u32 zaddr) {
    asm volatile("ldmatrix.sync.aligned.m8n8.x4.shared.b16 {%0,%1,%2,%3}, [%4];"
        : "=r"(zr[0]), "=r"(zr[1]), "=r"(zr[2]), "=r"(zr[3]) : "r"(zaddr));
}
__device__ __forceinline__ void ld_sm_x4_t(u32* zr, u32 zaddr) {
    asm volatile("ldmatrix.sync.aligned.m8n8.x4.trans.shared.b16 {%0,%1,%2,%3}, [%4];"
        : "=r"(zr[0]), "=r"(zr[1]), "=r"(zr[2]), "=r"(zr[3]) : "r"(zaddr));
}
__device__ __forceinline__ void mma16816(float* zc, const u32* za, u32 zb0, u32 zb1) {
    asm volatile("mma.sync.aligned.m16n8k16.row.col.f32.bf16.bf16.f32 "
        "{%0,%1,%2,%3},{%4,%5,%6,%7},{%8,%9},{%0,%1,%2,%3};"
        : "+f"(zc[0]), "+f"(zc[1]), "+f"(zc[2]), "+f"(zc[3])
        : "r"(za[0]), "r"(za[1]), "r"(za[2]), "r"(za[3]), "r"(zb0), "r"(zb1));
}

// ---------------------------------------------------------------------------
// prep: bx<512  : convert s2 -> (Ahi, Alo)
//       512..639: convert [w_s|hw1] -> (Whi,Wlo)
//       bx>=640 : preq[b] = q[b] @ w_q
// ---------------------------------------------------------------------------
__global__ void __launch_bounds__(256) prep_k(
    const float* __restrict__ s2, const float* __restrict__ w1,
    const float* __restrict__ hw1, const float* __restrict__ q,
    __nv_bfloat16* __restrict__ Ahi, __nv_bfloat16* __restrict__ Alo,
    __nv_bfloat16* __restrict__ Whi, __nv_bfloat16* __restrict__ Wlo,
    float* __restrict__ preq)
{
    const int ztid = threadIdx.x;
    const int zbx  = blockIdx.x;

    if (zbx < 512) {
        size_t zoff = ((size_t)zbx * 256 + ztid) * 8;
        float4 zva = *reinterpret_cast<const float4*>(s2 + zoff);
        float4 zvb = *reinterpret_cast<const float4*>(s2 + zoff + 4);
        float zv[8] = {zva.x,zva.y,zva.z,zva.w,zvb.x,zvb.y,zvb.z,zvb.w};
        __nv_bfloat16 zhi[8];
        __nv_bfloat16 zlo[8];
        #pragma unroll
        for (int zi = 0; zi < 8; zi++) {
            zhi[zi] = __float2bfloat16(zv[zi]);
            zlo[zi] = __float2bfloat16(zv[zi] - __bfloat162float(zhi[zi]));
        }
        *reinterpret_cast<uint4*>(Ahi + zoff) = *reinterpret_cast<uint4*>(zhi);
        *reinterpret_cast<uint4*>(Alo + zoff) = *reinterpret_cast<uint4*>(zlo);
        return;
    }
    if (zbx < 640) {
        size_t zoff = ((size_t)(zbx - 512) * 256 + ztid) * 8;
        const int zk = (int)(zoff >> 9);
        const int zn = (int)(zoff & 511);
        const float* zsrc = (zn < 256) ? (w1 + (size_t)zk*256 + zn)
                                       : (hw1 + (size_t)zk*256 + (zn - 256));
        float4 zva = *reinterpret_cast<const float4*>(zsrc);
        float4 zvb = *reinterpret_cast<const float4*>(zsrc + 4);
        float zv[8] = {zva.x,zva.y,zva.z,zva.w,zvb.x,zvb.y,zvb.z,zvb.w};
        __nv_bfloat16 zhi[8];
        __nv_bfloat16 zlo[8];
        #pragma unroll
        for (int zi = 0; zi < 8; zi++) {
            zhi[zi] = __float2bfloat16(zv[zi]);
            zlo[zi] = __float2bfloat16(zv[zi] - __bfloat162float(zhi[zi]));
        }
        *reinterpret_cast<uint4*>(Whi + zoff) = *reinterpret_cast<uint4*>(zhi);
        *reinterpret_cast<uint4*>(Wlo + zoff) = *reinterpret_cast<uint4*>(zlo);
        return;
    }
    __shared__ float zqs[DQ_];
    const int zb = zbx - 640;
    for (int zd = ztid; zd < DQ_; zd += 256) zqs[zd] = q[zb*DQ_ + zd];
    __syncthreads();
    const float* zwq = w1 + (size_t)(DS_ + DX_) * H_ + ztid;
    float zacc0 = 0.f;
    float zacc1 = 0.f;
    #pragma unroll 8
    for (int zd = 0; zd < DQ_; zd += 2) {
        zacc0 = fmaf(zqs[zd],   zwq[(size_t)zd*H_],     zacc0);
        zacc1 = fmaf(zqs[zd+1], zwq[(size_t)(zd+1)*H_], zacc1);
    }
    preq[zb*H_ + ztid] = zacc0 + zacc1;
}

// ---------------------------------------------------------------------------
// k1_mma: C[2048,512] = [ s2@w_s | relu(s2@hw1+hb1) ] via bf16x3 tensor MMA.
// ---------------------------------------------------------------------------
__global__ void __launch_bounds__(256) k1_mma(
    const __nv_bfloat16* __restrict__ Ahi, const __nv_bfloat16* __restrict__ Alo,
    const __nv_bfloat16* __restrict__ Whi, const __nv_bfloat16* __restrict__ Wlo,
    const float* __restrict__ hb1, float* __restrict__ C)
{
    __shared__ __align__(16) __nv_bfloat16 zSmemAhi[2][128][24];
    __shared__ __align__(16) __nv_bfloat16 zSmemAlo[2][128][24];
    __shared__ __align__(16) __nv_bfloat16 zSmemBhi[2][16][72];
    __shared__ __align__(16) __nv_bfloat16 zSmemBlo[2][16][72];

    const int ztid  = threadIdx.x;
    const int zbx   = blockIdx.x;
    const int zbm   = zbx >> 3;
    const int zbn   = zbx & 7;
    const int zm0   = zbm * 128;
    const int zn0   = zbn * 64;
    const int zwarp = ztid >> 5;
    const int zlane = ztid & 31;
    const int zwm   = zwarp & 3;
    const int zwn   = zwarp >> 2;

    const int zArow = ztid >> 1;
    const int zAseg = (ztid & 1) * 8;
    const __nv_bfloat16* zgAhi = Ahi + (size_t)(zm0 + zArow) * 512 + zAseg;
    const __nv_bfloat16* zgAlo = Alo + (size_t)(zm0 + zArow) * 512 + zAseg;
    const int zBrow = ztid >> 3;
    const int zBcol = (ztid & 7) * 8;
    const __nv_bfloat16* zgBhi = Whi + (size_t)zBrow * 512 + zn0 + zBcol;
    const __nv_bfloat16* zgBlo = Wlo + (size_t)zBrow * 512 + zn0 + zBcol;
    const bool zDoB = (ztid < 128);

    float zacc[2][4][4];
    #pragma unroll
    for (int zf = 0; zf < 2; zf++) {
        #pragma unroll
        for (int zg = 0; zg < 4; zg++) {
            #pragma unroll
            for (int ze = 0; ze < 4; ze++) zacc[zf][zg][ze] = 0.f;
        }
    }

    u32 zAddrAhi[2];
    u32 zAddrAlo[2];
    u32 zAddrBhi[2];
    u32 zAddrBlo[2];
    {
        const int zquad = zlane >> 3;
        const int zrow8 = zlane & 7;
        #pragma unroll
        for (int zf = 0; zf < 2; zf++) {
            const int zrr = zwm*32 + zf*16 + (zquad & 1)*8 + zrow8;
            const int zcc = (zquad >> 1) * 8;
            zAddrAhi[zf] = smem_addr_u32(&zSmemAhi[0][zrr][zcc]);
            zAddrAlo[zf] = smem_addr_u32(&zSmemAlo[0][zrr][zcc]);
        }
        #pragma unroll
        for (int zg16 = 0; zg16 < 2; zg16++) {
            const int zkr = (zquad & 1)*8 + zrow8;
            const int znc = zwn*32 + zg16*16 + (zquad >> 1)*8;
            zAddrBhi[zg16] = smem_addr_u32(&zSmemBhi[0][zkr][znc]);
            zAddrBlo[zg16] = smem_addr_u32(&zSmemBlo[0][zkr][znc]);
        }
    }
    const u32 zBytesBufA = (u32)(128*24*2);
    const u32 zBytesBufB = (u32)(16*72*2);

    uint4 zPfAhi = *reinterpret_cast<const uint4*>(zgAhi);
    uint4 zPfAlo = *reinterpret_cast<const uint4*>(zgAlo);
    uint4 zPfBhi = zDoB ? *reinterpret_cast<const uint4*>(zgBhi) : make_uint4(0,0,0,0);
    uint4 zPfBlo = zDoB ? *reinterpret_cast<const uint4*>(zgBlo) : make_uint4(0,0,0,0);
    *reinterpret_cast<uint4*>(&zSmemAhi[0][zArow][zAseg]) = zPfAhi;
    *reinterpret_cast<uint4*>(&zSmemAlo[0][zArow][zAseg]) = zPfAlo;
    if (zDoB) {
        *reinterpret_cast<uint4*>(&zSmemBhi[0][zBrow][zBcol]) = zPfBhi;
        *reinterpret_cast<uint4*>(&zSmemBlo[0][zBrow][zBcol]) = zPfBlo;
    }
    __syncthreads();

    #pragma unroll 1
    for (int zkt = 0; zkt < 32; zkt++) {
        const int zbuf = zkt & 1;
        if (zkt < 31) {
            zPfAhi = *reinterpret_cast<const uint4*>(zgAhi + (zkt+1)*16);
            zPfAlo = *reinterpret_cast<const uint4*>(zgAlo + (zkt+1)*16);
            if (zDoB) {
                zPfBhi = *reinterpret_cast<const uint4*>(zgBhi + (size_t)(zkt+1)*16*512);
                zPfBlo = *reinterpret_cast<const uint4*>(zgBlo + (size_t)(zkt+1)*16*512);
            }
        }
        u32 zFragAhi[2][4];
        u32 zFragAlo[2][4];
        u32 zFragBhi[2][4];
        u32 zFragBlo[2][4];
        #pragma unroll
        for (int zf = 0; zf < 2; zf++) {
            ld_sm_x4(zFragAhi[zf], zAddrAhi[zf] + zbuf*zBytesBufA);
            ld_sm_x4(zFragAlo[zf], zAddrAlo[zf] + zbuf*zBytesBufA);
        }
        #pragma unroll
        for (int zg16 = 0; zg16 < 2; zg16++) {
            ld_sm_x4_t(zFragBhi[zg16], zAddrBhi[zg16] + zbuf*zBytesBufB);
            ld_sm_x4_t(zFragBlo[zg16], zAddrBlo[zg16] + zbuf*zBytesBufB);
        }
        #pragma unroll
        for (int zf = 0; zf < 2; zf++) {
            #pragma unroll
            for (int zg = 0; zg < 4; zg++) {
                const int zg16  = zg >> 1;
                const int zhsel = (zg & 1) * 2;
                mma16816(zacc[zf][zg], zFragAhi[zf], zFragBhi[zg16][zhsel], zFragBhi[zg16][zhsel+1]);
                mma16816(zacc[zf][zg], zFragAhi[zf], zFragBlo[zg16][zhsel], zFragBlo[zg16][zhsel+1]);
                mma16816(zacc[zf][zg], zFragAlo[zf], zFragBhi[zg16][zhsel], zFragBhi[zg16][zhsel+1]);
            }
        }
        if (zkt < 31) {
            const int znb = zbuf ^ 1;
            *reinterpret_cast<uint4*>(&zSmemAhi[znb][zArow][zAseg]) = zPfAhi;
            *reinterpret_cast<uint4*>(&zSmemAlo[znb][zArow][zAseg]) = zPfAlo;
            if (zDoB) {
                *reinterpret_cast<uint4*>(&zSmemBhi[znb][zBrow][zBcol]) = zPfBhi;
                *reinterpret_cast<uint4*>(&zSmemBlo[znb][zBrow][zBcol]) = zPfBlo;
            }
        }
        __syncthreads();
    }

    const bool zRelu = (zn0 >= 256);
    #pragma unroll
    for (int zf = 0; zf < 2; zf++) {
        #pragma unroll
        for (int zg = 0; zg < 4; zg++) {
            const int zrow = zm0 + zwm*32 + zf*16 + (zlane >> 2);
            const int zcol = zn0 + zwn*32 + zg*8 + (zlane & 3)*2;
            float2 zv0 = make_float2(zacc[zf][zg][0], zacc[zf][zg][1]);
            float2 zv1 = make_float2(zacc[zf][zg][2], zacc[zf][zg][3]);
            if (zRelu) {
                float2 zbb = *reinterpret_cast<const float2*>(&hb1[zcol - 256]);
                zv0.x = fmaxf(zv0.x + zbb.x, 0.f); zv0.y = fmaxf(zv0.y + zbb.y, 0.f);
                zv1.x = fmaxf(zv1.x + zbb.x, 0.f); zv1.y = fmaxf(zv1.y + zbb.y, 0.f);
            }
            *reinterpret_cast<float2*>(&C[(size_t)zrow * 512 + zcol])       = zv0;
            *reinterpret_cast<float2*>(&C[(size_t)(zrow + 8) * 512 + zcol]) = zv1;
        }
    }
}

// ---------------------------------------------------------------------------
// k2: bx<64 : hs[2048,128] = h1 @ hw2 + hb2      (64x64 tiles, K=256)
//     bx>=64: base[1152,256] = x0@w_x + preq[row/36] + b1  (64x64, K=128)
// ---------------------------------------------------------------------------
__global__ void __launch_bounds__(256) k2(
    const float* __restrict__ C, const float* __restrict__ hw2,
    const float* __restrict__ hb2, const float* __restrict__ x0,
    const float* __restrict__ w1, const float* __restrict__ b1,
    const float* __restrict__ preq,
    float* __restrict__ hs, float* __restrict__ base)
{
    __shared__ float As[2][16][68];
    __shared__ float Bs[2][16][64];
    const int tid = threadIdx.x;
    const int bx  = blockIdx.x;

    const float* A; const float* Bp; int lda, ldb, nt, m0, n0, mode;
    if (bx < 64) {
        mode = 0; const int tm = bx >> 1, tn = bx & 1;
        m0 = tm*64; n0 = tn*64;
        A = C + 256; lda = 512; Bp = hw2; ldb = 128; nt = 256/16;
    } else {
        mode = 1; const int bb = bx - 64; const int tm = bb >> 2, tn = bb & 3;
        m0 = tm*64; n0 = tn*64;
        A = x0; lda = 128; Bp = w1 + (size_t)DS_*H_; ldb = 256; nt = 128/16;
    }

    const int tx = tid & 15, ty = tid >> 4;
    const int ar = tid >> 2;
    const int ac = (tid & 3) << 2;
    const int bkr = tid >> 4;
    const int bn4 = (tid & 15) << 2;

    const float* Ag = A  + (size_t)(m0 + ar) * lda + ac;
    const float* Bg = Bp + (size_t)bkr * ldb + n0 + bn4;

    float2 acc[2][4];
    #pragma unroll
    for (int i = 0; i < 2; i++) {
        #pragma unroll
        for (int j = 0; j < 4; j++) acc[i][j] = make_float2(0.f, 0.f);
    }

    float4 av = *reinterpret_cast<const float4*>(Ag);
    float4 bv = *reinterpret_cast<const float4*>(Bg);
    As[0][ac+0][ar] = av.x; As[0][ac+1][ar] = av.y;
    As[0][ac+2][ar] = av.z; As[0][ac+3][ar] = av.w;
    *reinterpret_cast<float4*>(&Bs[0][bkr][bn4]) = bv;
    __syncthreads();

    #pragma unroll 1
    for (int kt = 0; kt < nt; kt++) {
        const int buf = kt & 1;
        if (kt + 1 < nt) {
            av = *reinterpret_cast<const float4*>(Ag + (kt+1)*16);
            bv = *reinterpret_cast<const float4*>(Bg + (size_t)(kt+1)*16*ldb);
        }
        #pragma unroll
        for (int kk = 0; kk < 16; kk++) {
            float4 a4 = *reinterpret_cast<const float4*>(&As[buf][kk][ty*4]);
            float4 b4 = *reinterpret_cast<const float4*>(&Bs[buf][kk][tx*4]);
            float2 a2v[2] = {{a4.x,a4.y},{a4.z,a4.w}};
            float2 bd[4]  = {{b4.x,b4.x},{b4.y,b4.y},{b4.z,b4.z},{b4.w,b4.w}};
            #pragma unroll
            for (int i = 0; i < 2; i++) {
                #pragma unroll
                for (int j = 0; j < 4; j++)
                    fma2(acc[i][j], a2v[i], bd[j]);
            }
        }
        if (kt + 1 < nt) {
            const int nb = buf ^ 1;
            As[nb][ac+0][ar] = av.x; As[nb][ac+1][ar] = av.y;
            As[nb][ac+2][ar] = av.z; As[nb][ac+3][ar] = av.w;
            *reinterpret_cast<float4*>(&Bs[nb][bkr][bn4]) = bv;
        }
        __syncthreads();
    }

    if (mode == 0) {
        float4 bb = *reinterpret_cast<const float4*>(&hb2[n0 + tx*4]);
        float* Or = hs + (size_t)(m0 + ty*4) * DX_ + n0 + tx*4;
        #pragma unroll
        for (int i = 0; i < 2; i++) {
            float4 lo = make_float4(acc[i][0].x+bb.x, acc[i][1].x+bb.y, acc[i][2].x+bb.z, acc[i][3].x+bb.w);
            float4 hi = make_float4(acc[i][0].y+bb.x, acc[i][1].y+bb.y, acc[i][2].y+bb.z, acc[i][3].y+bb.w);
            *reinterpret_cast<float4*>(Or + (size_t)(2*i  )*DX_) = lo;
            *reinterpret_cast<float4*>(Or + (size_t)(2*i+1)*DX_) = hi;
        }
    } else {
        float4 bb = *reinterpret_cast<const float4*>(&b1[n0 + tx*4]);
        #pragma unroll
        for (int i = 0; i < 2; i++) {
            const int r0 = m0 + ty*4 + 2*i;
            float4 p0 = *reinterpret_cast<const float4*>(&preq[(r0   /Kk_)*H_ + n0 + tx*4]);
            float4 p1 = *reinterpret_cast<const float4*>(&preq[((r0+1)/Kk_)*H_ + n0 + tx*4]);
            float4 lo = make_float4(acc[i][0].x+bb.x+p0.x, acc[i][1].x+bb.y+p0.y,
                                    acc[i][2].x+bb.z+p0.z, acc[i][3].x+bb.w+p0.w);
            float4 hi = make_float4(acc[i][0].y+bb.x+p1.x, acc[i][1].y+bb.y+p1.y,
                                    acc[i][2].y+bb.z+p1.z, acc[i][3].y+bb.w+p1.w);
            *reinterpret_cast<float4*>(&base[(size_t)(r0  )*H_ + n0 + tx*4]) = lo;
            *reinterpret_cast<float4*>(&base[(size_t)(r0+1)*H_ + n0 + tx*4]) = hi;
        }
    }
}

// ---------------------------------------------------------------------------
// att v3: 2 k per block (576 blocks, ~4/SM). Logits: pre_s chunk in smem as
//   XOR-swizzled float4 (conflict-free LDS.128), h split across 2 thread
//   groups, 4 independent accumulators. No warp reductions for logits.
// ---------------------------------------------------------------------------
__global__ void __launch_bounds__(256) att_k(
    const float* __restrict__ Cmat, const float* __restrict__ base,
    const float* __restrict__ hsm, const float* __restrict__ w2,
    const float* __restrict__ x0, float* __restrict__ out)
{
    const int b  = blockIdx.x / 18;
    const int kg = blockIdx.x % 18;
    const int bk0 = b * Kk_ + kg * 2;
    const int tid = threadIdx.x;
    const int warp = tid >> 5, lane = tid & 31;

    __shared__ __align__(16) float sbuf[64*130];   // 33KB; float4[64][32] swizzled OR [32][130]
    __shared__ float base_s[2][H_];
    __shared__ float w2s[H_];
    __shared__ float lpart[2][2][M_];              // [hh][km][mm]
    __shared__ float ew[2][M_];
    __shared__ float sinv[2];

    // base_s (2 rows) + w2s
    {
        const int i0 = tid;
        base_s[i0 >> 8][i0 & 255] = base[(size_t)(bk0 + (i0 >> 8)) * H_ + (i0 & 255)];
        const int i1 = tid + 256;
        base_s[i1 >> 8][i1 & 255] = base[(size_t)(bk0 + (i1 >> 8)) * H_ + (i1 & 255)];
        w2s[tid] = w2[tid];
    }

    const int hh = tid >> 7;           // h-half 0/1
    const int km = (tid >> 6) & 1;     // k 0/1 (uniform per warp)
    const int mm = tid & 63;           // m 0..63
    const float* pres = Cmat + (size_t)(b * M_) * 512;
    float4* f4buf = reinterpret_cast<float4*>(sbuf);

    float a0 = 0.f, a1 = 0.f, a2 = 0.f, a3 = 0.f;
    #pragma unroll 1
    for (int c = 0; c < 2; c++) {
        __syncthreads();
        // load pre_s[0:64][c*128:(c+1)*128] -> swizzled float4 [row][j^(row&7)]
        #pragma unroll
        for (int i = 0; i < 8; i++) {
            const int fi  = tid + i * 256;        // 0..2047
            const int row = fi >> 5;              // 32 f4 per row
            const int j   = fi & 31;
            float4 v = *reinterpret_cast<const float4*>(pres + (size_t)row * 512 + c * 128 + j * 4);
            f4buf[row * 32 + (j ^ (row & 7))] = v;
        }
        __syncthreads();
        const int jbase = hh * 16;
        const float* bs = &base_s[km][c * 128 + hh * 64];
        const float* ws = &w2s[c * 128 + hh * 64];
        #pragma unroll
        for (int jj = 0; jj < 16; jj++) {
            float4 v  = f4buf[mm * 32 + ((jbase + jj) ^ (mm & 7))];
            float4 bb = *reinterpret_cast<const float4*>(bs + jj * 4);
            float4 ww = *reinterpret_cast<const float4*>(ws + jj * 4);
            a0 = fmaf(fmaxf(v.x + bb.x, 0.f), ww.x, a0);
            a1 = fmaf(fmaxf(v.y + bb.y, 0.f), ww.y, a1);
            a2 = fmaf(fmaxf(v.z + bb.z, 0.f), ww.z, a2);
            a3 = fmaf(fmaxf(v.w + bb.w, 0.f), ww.w, a3);
        }
    }
    lpart[hh][km][mm] = (a0 + a1) + (a2 + a3);
    __syncthreads();

    // combine halves + softmax over m (warps 0/1 = k 0/1)
    if (warp < 2) {
        const int k = warp;
        float l0 = lpart[0][k][lane]      + lpart[1][k][lane];
        float l1 = lpart[0][k][lane + 32] + lpart[1][k][lane + 32];
        float mx = fmaxf(l0, l1);
        #pragma unroll
        for (int off = 16; off; off >>= 1)
            mx = fmaxf(mx, __shfl_xor_sync(0xffffffffu, mx, off));
        float e0 = expf(l0 - mx), e1 = expf(l1 - mx);
        float s = e0 + e1;
        #pragma unroll
        for (int off = 16; off; off >>= 1)
            s += __shfl_xor_sync(0xffffffffu, s, off);
        ew[k][lane] = e0; ew[k][lane + 32] = e1;
        if (lane == 0) sinv[k] = 1.f / s;
    }

    // aggregation: thread = (kp, f); hs staged in smem stride 130
    const int f  = tid & 127;
    const int kp = tid >> 7;
    float za = 0.f, zb = 0.f;
    const float* hsb = hsm + (size_t)(b * M_) * DX_;
    #pragma unroll 1
    for (int mc = 0; mc < 2; mc++) {
        __syncthreads();
        #pragma unroll
        for (int i = 0; i < 4; i++) {
            const int fi  = tid + i * 256;       // 0..1023
            const int row = fi >> 5;
            const int c4  = (fi & 31) * 4;
            float4 v = *reinterpret_cast<const float4*>(hsb + (size_t)(mc * 32 + row) * DX_ + c4);
            float* d = &sbuf[row * 130 + c4];
            d[0] = v.x; d[1] = v.y; d[2] = v.z; d[3] = v.w;
        }
        __syncthreads();
        const float* ep = &ew[kp][mc * 32];
        #pragma unroll 8
        for (int m = 0; m < 32; m += 2) {
            za = fmaf(ep[m],     sbuf[m * 130 + f],       za);
            zb = fmaf(ep[m + 1], sbuf[(m + 1) * 130 + f], zb);
        }
    }
    out[(size_t)(bk0 + kp) * 256 + 128 + f] = (za + zb) * sinv[kp];

    // x0 copy (2 * 128 = 256 elements)
    {
        const int k = tid >> 7, ff = tid & 127;
        out[(size_t)(bk0 + k) * 256 + ff] = x0[(size_t)(bk0 + k) * DX_ + ff];
    }
}

// ---------------------------------------------------------------------------
extern "C" void kernel_launch(void* const* d_in, const int* in_sizes, int n_in,
                              void* d_out, int out_size)
{
    (void)in_sizes; (void)n_in; (void)out_size;
    const float* s2  = (const float*)d_in[0];
    const float* x0  = (const float*)d_in[1];
    const float* q   = (const float*)d_in[2];
    const float* w1  = (const float*)d_in[3];
    const float* b1  = (const float*)d_in[4];
    const float* w2  = (const float*)d_in[5];
    const float* hw1 = (const float*)d_in[7];
    const float* hb1 = (const float*)d_in[8];
    const float* hw2 = (const float*)d_in[9];
    const float* hb2 = (const float*)d_in[10];
    float* out = (float*)d_out;

    float *preq, *C, *hs, *base;
    __nv_bfloat16 *Ahi, *Alo, *Whi, *Wlo;
    cudaGetSymbolAddress((void**)&preq, g_preq);
    cudaGetSymbolAddress((void**)&C,    g_C);
    cudaGetSymbolAddress((void**)&hs,   g_hs);
    cudaGetSymbolAddress((void**)&base, g_base);
    cudaGetSymbolAddress((void**)&Ahi,  g_Ahi);
    cudaGetSymbolAddress((void**)&Alo,  g_Alo);
    cudaGetSymbolAddress((void**)&Whi,  g_Whi);
    cudaGetSymbolAddress((void**)&Wlo,  g_Wlo);

    // P: bf16 hi/lo split of s2 and [w_s|hw1], + preq
    prep_k<<<672, 256>>>(s2, w1, hw1, q, Ahi, Alo, Whi, Wlo, preq);
    // L1: tensor-core bf16x3 GEMM -> C (relu+hb1 fused for cols>=256)
    k1_mma<<<128, 256>>>(Ahi, Alo, Whi, Wlo, hb1, C);
    // L2: hs + base
    k2<<<136, 256>>>(C, hw2, hb2, x0, w1, b1, preq, hs, base);
    // L3: fused attention + output (2k/block, swizzled float4 staging)
    att_k<<<576, 256>>>(C, base, hs, w2, x0, out);
}

// round 14
// speedup vs baseline: 1.0366x; 1.0366x over previous
#include <cuda_runtime.h>
#include <cuda_bf16.h>
#include <cstdint>
#include <math.h>

typedef unsigned int u32;

#define B_  32
#define M_  64
#define Kk_ 36
#define DS_ 512
#define DX_ 128
#define DQ_ 512
#define H_  256
#define ROWS_S 2048
#define ROWS_X 1152

// Scratch (allocation-free rule: __device__ globals)
__device__ __align__(16) float g_preq[B_*H_];
__device__ __align__(16) float g_C[ROWS_S*512];      // 0:256 pre_s (raw), 256:512 h1=relu(..+hb1)
__device__ __align__(16) float g_hs[ROWS_S*DX_];
__device__ __align__(16) float g_base[ROWS_X*H_];
__device__ __align__(16) __nv_bfloat16 g_Ahi[ROWS_S*512];
__device__ __align__(16) __nv_bfloat16 g_Alo[ROWS_S*512];
__device__ __align__(16) __nv_bfloat16 g_Whi[512*512];  // cols 0:256 w_s, 256:512 hw1
__device__ __align__(16) __nv_bfloat16 g_Wlo[512*512];

__device__ __forceinline__ void fma2(float2 &d, const float2 &a, const float2 &b) {
    asm("fma.rn.f32x2 %0, %1, %2, %0;"
        : "+l"(reinterpret_cast<unsigned long long&>(d))
        : "l"(reinterpret_cast<const unsigned long long&>(a)),
          "l"(reinterpret_cast<const unsigned long long&>(b)));
}

__device__ __forceinline__ u32 smem_addr_u32(const void* zp) {
    return (u32)__cvta_generic_to_shared(zp);
}
__device__ __forceinline__ void ld_sm_x4(u32* zr, u32 zaddr) {
    asm volatile("ldmatrix.sync.aligned.m8n8.x4.shared.b16 {%0,%1,%2,%3}, [%4];"
        : "=r"(zr[0]), "=r"(zr[1]), "=r"(zr[2]), "=r"(zr[3]) : "r"(zaddr));
}
__device__ __forceinline__ void ld_sm_x4_t(u32* zr, u32 zaddr) {
    asm volatile("ldmatrix.sync.aligned.m8n8.x4.trans.shared.b16 {%0,%1,%2,%3}, [%4];"
        : "=r"(zr[0]), "=r"(zr[1]), "=r"(zr[2]), "=r"(zr[3]) : "r"(zaddr));
}
__device__ __forceinline__ void mma16816(float* zc, const u32* za, u32 zb0, u32 zb1) {
    asm volatile("mma.sync.aligned.m16n8k16.row.col.f32.bf16.bf16.f32 "
        "{%0,%1,%2,%3},{%4,%5,%6,%7},{%8,%9},{%0,%1,%2,%3};"
        : "+f"(zc[0]), "+f"(zc[1]), "+f"(zc[2]), "+f"(zc[3])
        : "r"(za[0]), "r"(za[1]), "r"(za[2]), "r"(za[3]), "r"(zb0), "r"(zb1));
}

// ---------------------------------------------------------------------------
// prep: bx<512  : convert s2 -> (Ahi, Alo)
//       512..639: convert [w_s|hw1] -> (Whi,Wlo)
//       bx>=640 : preq[b] = q[b] @ w_q
// ---------------------------------------------------------------------------
__global__ void __launch_bounds__(256) prep_k(
    const float* __restrict__ s2, const float* __restrict__ w1,
    const float* __restrict__ hw1, const float* __restrict__ q,
    __nv_bfloat16* __restrict__ Ahi, __nv_bfloat16* __restrict__ Alo,
    __nv_bfloat16* __restrict__ Whi, __nv_bfloat16* __restrict__ Wlo,
    float* __restrict__ preq)
{
    const int ztid = threadIdx.x;
    const int zbx  = blockIdx.x;

    if (zbx < 512) {
        size_t zoff = ((size_t)zbx * 256 + ztid) * 8;
        float4 zva = *reinterpret_cast<const float4*>(s2 + zoff);
        float4 zvb = *reinterpret_cast<const float4*>(s2 + zoff + 4);
        float zv[8] = {zva.x,zva.y,zva.z,zva.w,zvb.x,zvb.y,zvb.z,zvb.w};
        __nv_bfloat16 zhi[8];
        __nv_bfloat16 zlo[8];
        #pragma unroll
        for (int zi = 0; zi < 8; zi++) {
            zhi[zi] = __float2bfloat16(zv[zi]);
            zlo[zi] = __float2bfloat16(zv[zi] - __bfloat162float(zhi[zi]));
        }
        *reinterpret_cast<uint4*>(Ahi + zoff) = *reinterpret_cast<uint4*>(zhi);
        *reinterpret_cast<uint4*>(Alo + zoff) = *reinterpret_cast<uint4*>(zlo);
        return;
    }
    if (zbx < 640) {
        size_t zoff = ((size_t)(zbx - 512) * 256 + ztid) * 8;
        const int zk = (int)(zoff >> 9);
        const int zn = (int)(zoff & 511);
        const float* zsrc = (zn < 256) ? (w1 + (size_t)zk*256 + zn)
                                       : (hw1 + (size_t)zk*256 + (zn - 256));
        float4 zva = *reinterpret_cast<const float4*>(zsrc);
        float4 zvb = *reinterpret_cast<const float4*>(zsrc + 4);
        float zv[8] = {zva.x,zva.y,zva.z,zva.w,zvb.x,zvb.y,zvb.z,zvb.w};
        __nv_bfloat16 zhi[8];
        __nv_bfloat16 zlo[8];
        #pragma unroll
        for (int zi = 0; zi < 8; zi++) {
            zhi[zi] = __float2bfloat16(zv[zi]);
            zlo[zi] = __float2bfloat16(zv[zi] - __bfloat162float(zhi[zi]));
        }
        *reinterpret_cast<uint4*>(Whi + zoff) = *reinterpret_cast<uint4*>(zhi);
        *reinterpret_cast<uint4*>(Wlo + zoff) = *reinterpret_cast<uint4*>(zlo);
        return;
    }
    __shared__ float zqs[DQ_];
    const int zb = zbx - 640;
    for (int zd = ztid; zd < DQ_; zd += 256) zqs[zd] = q[zb*DQ_ + zd];
    __syncthreads();
    const float* zwq = w1 + (size_t)(DS_ + DX_) * H_ + ztid;
    float zacc0 = 0.f;
    float zacc1 = 0.f;
    #pragma unroll 8
    for (int zd = 0; zd < DQ_; zd += 2) {
        zacc0 = fmaf(zqs[zd],   zwq[(size_t)zd*H_],     zacc0);
        zacc1 = fmaf(zqs[zd+1], zwq[(size_t)(zd+1)*H_], zacc1);
    }
    preq[zb*H_ + ztid] = zacc0 + zacc1;
}

// ---------------------------------------------------------------------------
// k1_mma: C[2048,512] = [ s2@w_s | relu(s2@hw1+hb1) ] via bf16x3 tensor MMA.
// ---------------------------------------------------------------------------
__global__ void __launch_bounds__(256) k1_mma(
    const __nv_bfloat16* __restrict__ Ahi, const __nv_bfloat16* __restrict__ Alo,
    const __nv_bfloat16* __restrict__ Whi, const __nv_bfloat16* __restrict__ Wlo,
    const float* __restrict__ hb1, float* __restrict__ C)
{
    __shared__ __align__(16) __nv_bfloat16 zSmemAhi[2][128][24];
    __shared__ __align__(16) __nv_bfloat16 zSmemAlo[2][128][24];
    __shared__ __align__(16) __nv_bfloat16 zSmemBhi[2][16][72];
    __shared__ __align__(16) __nv_bfloat16 zSmemBlo[2][16][72];

    const int ztid  = threadIdx.x;
    const int zbx   = blockIdx.x;
    const int zbm   = zbx >> 3;
    const int zbn   = zbx & 7;
    const int zm0   = zbm * 128;
    const int zn0   = zbn * 64;
    const int zwarp = ztid >> 5;
    const int zlane = ztid & 31;
    const int zwm   = zwarp & 3;
    const int zwn   = zwarp >> 2;

    const int zArow = ztid >> 1;
    const int zAseg = (ztid & 1) * 8;
    const __nv_bfloat16* zgAhi = Ahi + (size_t)(zm0 + zArow) * 512 + zAseg;
    const __nv_bfloat16* zgAlo = Alo + (size_t)(zm0 + zArow) * 512 + zAseg;
    const int zBrow = ztid >> 3;
    const int zBcol = (ztid & 7) * 8;
    const __nv_bfloat16* zgBhi = Whi + (size_t)zBrow * 512 + zn0 + zBcol;
    const __nv_bfloat16* zgBlo = Wlo + (size_t)zBrow * 512 + zn0 + zBcol;
    const bool zDoB = (ztid < 128);

    float zacc[2][4][4];
    #pragma unroll
    for (int zf = 0; zf < 2; zf++) {
        #pragma unroll
        for (int zg = 0; zg < 4; zg++) {
            #pragma unroll
            for (int ze = 0; ze < 4; ze++) zacc[zf][zg][ze] = 0.f;
        }
    }

    u32 zAddrAhi[2];
    u32 zAddrAlo[2];
    u32 zAddrBhi[2];
    u32 zAddrBlo[2];
    {
        const int zquad = zlane >> 3;
        const int zrow8 = zlane & 7;
        #pragma unroll
        for (int zf = 0; zf < 2; zf++) {
            const int zrr = zwm*32 + zf*16 + (zquad & 1)*8 + zrow8;
            const int zcc = (zquad >> 1) * 8;
            zAddrAhi[zf] = smem_addr_u32(&zSmemAhi[0][zrr][zcc]);
            zAddrAlo[zf] = smem_addr_u32(&zSmemAlo[0][zrr][zcc]);
        }
        #pragma unroll
        for (int zg16 = 0; zg16 < 2; zg16++) {
            const int zkr = (zquad & 1)*8 + zrow8;
            const int znc = zwn*32 + zg16*16 + (zquad >> 1)*8;
            zAddrBhi[zg16] = smem_addr_u32(&zSmemBhi[0][zkr][znc]);
            zAddrBlo[zg16] = smem_addr_u32(&zSmemBlo[0][zkr][znc]);
        }
    }
    const u32 zBytesBufA = (u32)(128*24*2);
    const u32 zBytesBufB = (u32)(16*72*2);

    uint4 zPfAhi = *reinterpret_cast<const uint4*>(zgAhi);
    uint4 zPfAlo = *reinterpret_cast<const uint4*>(zgAlo);
    uint4 zPfBhi = zDoB ? *reinterpret_cast<const uint4*>(zgBhi) : make_uint4(0,0,0,0);
    uint4 zPfBlo = zDoB ? *reinterpret_cast<const uint4*>(zgBlo) : make_uint4(0,0,0,0);
    *reinterpret_cast<uint4*>(&zSmemAhi[0][zArow][zAseg]) = zPfAhi;
    *reinterpret_cast<uint4*>(&zSmemAlo[0][zArow][zAseg]) = zPfAlo;
    if (zDoB) {
        *reinterpret_cast<uint4*>(&zSmemBhi[0][zBrow][zBcol]) = zPfBhi;
        *reinterpret_cast<uint4*>(&zSmemBlo[0][zBrow][zBcol]) = zPfBlo;
    }
    __syncthreads();

    #pragma unroll 1
    for (int zkt = 0; zkt < 32; zkt++) {
        const int zbuf = zkt & 1;
        if (zkt < 31) {
            zPfAhi = *reinterpret_cast<const uint4*>(zgAhi + (zkt+1)*16);
            zPfAlo = *reinterpret_cast<const uint4*>(zgAlo + (zkt+1)*16);
            if (zDoB) {
                zPfBhi = *reinterpret_cast<const uint4*>(zgBhi + (size_t)(zkt+1)*16*512);
                zPfBlo = *reinterpret_cast<const uint4*>(zgBlo + (size_t)(zkt+1)*16*512);
            }
        }
        u32 zFragAhi[2][4];
        u32 zFragAlo[2][4];
        u32 zFragBhi[2][4];
        u32 zFragBlo[2][4];
        #pragma unroll
        for (int zf = 0; zf < 2; zf++) {
            ld_sm_x4(zFragAhi[zf], zAddrAhi[zf] + zbuf*zBytesBufA);
            ld_sm_x4(zFragAlo[zf], zAddrAlo[zf] + zbuf*zBytesBufA);
        }
        #pragma unroll
        for (int zg16 = 0; zg16 < 2; zg16++) {
            ld_sm_x4_t(zFragBhi[zg16], zAddrBhi[zg16] + zbuf*zBytesBufB);
            ld_sm_x4_t(zFragBlo[zg16], zAddrBlo[zg16] + zbuf*zBytesBufB);
        }
        #pragma unroll
        for (int zf = 0; zf < 2; zf++) {
            #pragma unroll
            for (int zg = 0; zg < 4; zg++) {
                const int zg16  = zg >> 1;
                const int zhsel = (zg & 1) * 2;
                mma16816(zacc[zf][zg], zFragAhi[zf], zFragBhi[zg16][zhsel], zFragBhi[zg16][zhsel+1]);
                mma16816(zacc[zf][zg], zFragAhi[zf], zFragBlo[zg16][zhsel], zFragBlo[zg16][zhsel+1]);
                mma16816(zacc[zf][zg], zFragAlo[zf], zFragBhi[zg16][zhsel], zFragBhi[zg16][zhsel+1]);
            }
        }
        if (zkt < 31) {
            const int znb = zbuf ^ 1;
            *reinterpret_cast<uint4*>(&zSmemAhi[znb][zArow][zAseg]) = zPfAhi;
            *reinterpret_cast<uint4*>(&zSmemAlo[znb][zArow][zAseg]) = zPfAlo;
            if (zDoB) {
                *reinterpret_cast<uint4*>(&zSmemBhi[znb][zBrow][zBcol]) = zPfBhi;
                *reinterpret_cast<uint4*>(&zSmemBlo[znb][zBrow][zBcol]) = zPfBlo;
            }
        }
        __syncthreads();
    }

    const bool zRelu = (zn0 >= 256);
    #pragma unroll
    for (int zf = 0; zf < 2; zf++) {
        #pragma unroll
        for (int zg = 0; zg < 4; zg++) {
            const int zrow = zm0 + zwm*32 + zf*16 + (zlane >> 2);
            const int zcol = zn0 + zwn*32 + zg*8 + (zlane & 3)*2;
            float2 zv0 = make_float2(zacc[zf][zg][0], zacc[zf][zg][1]);
            float2 zv1 = make_float2(zacc[zf][zg][2], zacc[zf][zg][3]);
            if (zRelu) {
                float2 zbb = *reinterpret_cast<const float2*>(&hb1[zcol - 256]);
                zv0.x = fmaxf(zv0.x + zbb.x, 0.f); zv0.y = fmaxf(zv0.y + zbb.y, 0.f);
                zv1.x = fmaxf(zv1.x + zbb.x, 0.f); zv1.y = fmaxf(zv1.y + zbb.y, 0.f);
            }
            *reinterpret_cast<float2*>(&C[(size_t)zrow * 512 + zcol])       = zv0;
            *reinterpret_cast<float2*>(&C[(size_t)(zrow + 8) * 512 + zcol]) = zv1;
        }
    }
}

// ---------------------------------------------------------------------------
// k2: bx<64 : hs[2048,128] = h1 @ hw2 + hb2      (64x64 tiles, K=256)
//     bx>=64: base[1152,256] = x0@w_x + preq[row/36] + b1  (64x64, K=128)
// ---------------------------------------------------------------------------
__global__ void __launch_bounds__(256) k2(
    const float* __restrict__ C, const float* __restrict__ hw2,
    const float* __restrict__ hb2, const float* __restrict__ x0,
    const float* __restrict__ w1, const float* __restrict__ b1,
    const float* __restrict__ preq,
    float* __restrict__ hs, float* __restrict__ base)
{
    __shared__ float As[2][16][68];
    __shared__ float Bs[2][16][64];
    const int tid = threadIdx.x;
    const int bx  = blockIdx.x;

    const float* A; const float* Bp; int lda, ldb, nt, m0, n0, mode;
    if (bx < 64) {
        mode = 0; const int tm = bx >> 1, tn = bx & 1;
        m0 = tm*64; n0 = tn*64;
        A = C + 256; lda = 512; Bp = hw2; ldb = 128; nt = 256/16;
    } else {
        mode = 1; const int bb = bx - 64; const int tm = bb >> 2, tn = bb & 3;
        m0 = tm*64; n0 = tn*64;
        A = x0; lda = 128; Bp = w1 + (size_t)DS_*H_; ldb = 256; nt = 128/16;
    }

    const int tx = tid & 15, ty = tid >> 4;
    const int ar = tid >> 2;
    const int ac = (tid & 3) << 2;
    const int bkr = tid >> 4;
    const int bn4 = (tid & 15) << 2;

    const float* Ag = A  + (size_t)(m0 + ar) * lda + ac;
    const float* Bg = Bp + (size_t)bkr * ldb + n0 + bn4;

    float2 acc[2][4];
    #pragma unroll
    for (int i = 0; i < 2; i++) {
        #pragma unroll
        for (int j = 0; j < 4; j++) acc[i][j] = make_float2(0.f, 0.f);
    }

    float4 av = *reinterpret_cast<const float4*>(Ag);
    float4 bv = *reinterpret_cast<const float4*>(Bg);
    As[0][ac+0][ar] = av.x; As[0][ac+1][ar] = av.y;
    As[0][ac+2][ar] = av.z; As[0][ac+3][ar] = av.w;
    *reinterpret_cast<float4*>(&Bs[0][bkr][bn4]) = bv;
    __syncthreads();

    #pragma unroll 1
    for (int kt = 0; kt < nt; kt++) {
        const int buf = kt & 1;
        if (kt + 1 < nt) {
            av = *reinterpret_cast<const float4*>(Ag + (kt+1)*16);
            bv = *reinterpret_cast<const float4*>(Bg + (size_t)(kt+1)*16*ldb);
        }
        #pragma unroll
        for (int kk = 0; kk < 16; kk++) {
            float4 a4 = *reinterpret_cast<const float4*>(&As[buf][kk][ty*4]);
            float4 b4 = *reinterpret_cast<const float4*>(&Bs[buf][kk][tx*4]);
            float2 a2v[2] = {{a4.x,a4.y},{a4.z,a4.w}};
            float2 bd[4]  = {{b4.x,b4.x},{b4.y,b4.y},{b4.z,b4.z},{b4.w,b4.w}};
            #pragma unroll
            for (int i = 0; i < 2; i++) {
                #pragma unroll
                for (int j = 0; j < 4; j++)
                    fma2(acc[i][j], a2v[i], bd[j]);
            }
        }
        if (kt + 1 < nt) {
            const int nb = buf ^ 1;
            As[nb][ac+0][ar] = av.x; As[nb][ac+1][ar] = av.y;
            As[nb][ac+2][ar] = av.z; As[nb][ac+3][ar] = av.w;
            *reinterpret_cast<float4*>(&Bs[nb][bkr][bn4]) = bv;
        }
        __syncthreads();
    }

    if (mode == 0) {
        float4 bb = *reinterpret_cast<const float4*>(&hb2[n0 + tx*4]);
        float* Or = hs + (size_t)(m0 + ty*4) * DX_ + n0 + tx*4;
        #pragma unroll
        for (int i = 0; i < 2; i++) {
            float4 lo = make_float4(acc[i][0].x+bb.x, acc[i][1].x+bb.y, acc[i][2].x+bb.z, acc[i][3].x+bb.w);
            float4 hi = make_float4(acc[i][0].y+bb.x, acc[i][1].y+bb.y, acc[i][2].y+bb.z, acc[i][3].y+bb.w);
            *reinterpret_cast<float4*>(Or + (size_t)(2*i  )*DX_) = lo;
            *reinterpret_cast<float4*>(Or + (size_t)(2*i+1)*DX_) = hi;
        }
    } else {
        float4 bb = *reinterpret_cast<const float4*>(&b1[n0 + tx*4]);
        #pragma unroll
        for (int i = 0; i < 2; i++) {
            const int r0 = m0 + ty*4 + 2*i;
            float4 p0 = *reinterpret_cast<const float4*>(&preq[(r0   /Kk_)*H_ + n0 + tx*4]);
            float4 p1 = *reinterpret_cast<const float4*>(&preq[((r0+1)/Kk_)*H_ + n0 + tx*4]);
            float4 lo = make_float4(acc[i][0].x+bb.x+p0.x, acc[i][1].x+bb.y+p0.y,
                                    acc[i][2].x+bb.z+p0.z, acc[i][3].x+bb.w+p0.w);
            float4 hi = make_float4(acc[i][0].y+bb.x+p1.x, acc[i][1].y+bb.y+p1.y,
                                    acc[i][2].y+bb.z+p1.z, acc[i][3].y+bb.w+p1.w);
            *reinterpret_cast<float4*>(&base[(size_t)(r0  )*H_ + n0 + tx*4]) = lo;
            *reinterpret_cast<float4*>(&base[(size_t)(r0+1)*H_ + n0 + tx*4]) = hi;
        }
    }
}

// ---------------------------------------------------------------------------
// att v4: 4 k per block (288 blocks), smem-staged pre_s at stride 68
//   (float4-aligned, conflict-free), inner loop = 16 x LDS.128 with 4
//   independent accumulator chains. Aggregation as in v2.
// ---------------------------------------------------------------------------
__global__ void __launch_bounds__(256) att_k(
    const float* __restrict__ Cmat, const float* __restrict__ base,
    const float* __restrict__ hsm, const float* __restrict__ w2,
    const float* __restrict__ x0, float* __restrict__ out)
{
    const int b  = blockIdx.x / 9;
    const int kg = blockIdx.x % 9;
    const int bk0 = b * Kk_ + kg * 4;
    const int tid = threadIdx.x;
    const int warp = tid >> 5, lane = tid & 31;

    __shared__ __align__(16) float sbuf[64*68];    // 17.4KB; pre_s [64][68] / hs [32][130]
    __shared__ float base_s[4][H_];
    __shared__ float w2s[H_];
    __shared__ float lgt[4][M_];
    __shared__ float ew[4][M_];
    __shared__ float sinv[4];

    for (int idx = tid; idx < 4*H_; idx += 256)
        base_s[idx >> 8][idx & 255] = base[(size_t)(bk0 + (idx >> 8)) * H_ + (idx & 255)];
    w2s[tid] = w2[tid];

    const int km = tid >> 6;     // k index 0..3
    const int mm = tid & 63;     // m index 0..63
    const float* pres = Cmat + (size_t)(b * M_) * 512;

    float a0 = 0.f, a1 = 0.f, a2 = 0.f, a3 = 0.f;
    #pragma unroll 1
    for (int hc = 0; hc < 4; hc++) {
        __syncthreads();
        // cooperative load pre_s[0:64][hc*64 : hc*64+64] -> sbuf stride 68
        #pragma unroll
        for (int i = 0; i < 4; i++) {
            const int fi  = tid + i * 256;       // 0..1023 float4 idx
            const int row = fi >> 4;             // 16 float4 per row
            const int c4  = (fi & 15) * 4;
            float4 v = *reinterpret_cast<const float4*>(pres + (size_t)row * 512 + hc * 64 + c4);
            *reinterpret_cast<float4*>(&sbuf[row * 68 + c4]) = v;
        }
        __syncthreads();
        const float* srow = &sbuf[mm * 68];
        const float* bs   = &base_s[km][hc * 64];
        const float* ws   = &w2s[hc * 64];
        #pragma unroll
        for (int jj = 0; jj < 16; jj++) {
            float4 v  = *reinterpret_cast<const float4*>(srow + jj * 4);
            float4 bb = *reinterpret_cast<const float4*>(bs + jj * 4);
            float4 ww = *reinterpret_cast<const float4*>(ws + jj * 4);
            a0 = fmaf(fmaxf(v.x + bb.x, 0.f), ww.x, a0);
            a1 = fmaf(fmaxf(v.y + bb.y, 0.f), ww.y, a1);
            a2 = fmaf(fmaxf(v.z + bb.z, 0.f), ww.z, a2);
            a3 = fmaf(fmaxf(v.w + bb.w, 0.f), ww.w, a3);
        }
    }
    lgt[km][mm] = (a0 + a1) + (a2 + a3);
    __syncthreads();

    if (warp < 4) {
        const int k = warp;
        float l0 = lgt[k][lane], l1 = lgt[k][lane + 32];
        float mx = fmaxf(l0, l1);
        #pragma unroll
        for (int off = 16; off; off >>= 1)
            mx = fmaxf(mx, __shfl_xor_sync(0xffffffffu, mx, off));
        float e0 = expf(l0 - mx), e1 = expf(l1 - mx);
        float s = e0 + e1;
        #pragma unroll
        for (int off = 16; off; off >>= 1)
            s += __shfl_xor_sync(0xffffffffu, s, off);
        ew[k][lane] = e0; ew[k][lane + 32] = e1;
        if (lane == 0) sinv[k] = 1.f / s;
    }

    // aggregation: thread = (kp, f); hs staged in smem, stride 130
    const int f  = tid & 127;
    const int kp = tid >> 7;
    const int k0 = kp * 2, k1 = k0 + 1;
    float za0 = 0.f, za1 = 0.f, zb0 = 0.f, zb1 = 0.f;
    const float* hsb = hsm + (size_t)(b * M_) * DX_;
    #pragma unroll 1
    for (int mc = 0; mc < 2; mc++) {
        __syncthreads();
        #pragma unroll
        for (int i = 0; i < 4; i++) {
            const int fi  = tid + i * 256;       // 0..1023 float4 idx
            const int row = fi >> 5;             // 32 float4 per row
            const int c4  = (fi & 31) * 4;
            float4 v = *reinterpret_cast<const float4*>(hsb + (size_t)(mc * 32 + row) * DX_ + c4);
            float* d = &sbuf[row * 130 + c4];
            d[0] = v.x; d[1] = v.y; d[2] = v.z; d[3] = v.w;
        }
        __syncthreads();
        const float* e0p = &ew[k0][mc * 32];
        const float* e1p = &ew[k1][mc * 32];
        #pragma unroll 8
        for (int m = 0; m < 32; m += 2) {
            const float v0 = sbuf[m * 130 + f];
            const float v1 = sbuf[(m + 1) * 130 + f];
            za0 = fmaf(e0p[m],     v0, za0);
            za1 = fmaf(e0p[m + 1], v1, za1);
            zb0 = fmaf(e1p[m],     v0, zb0);
            zb1 = fmaf(e1p[m + 1], v1, zb1);
        }
    }
    out[(size_t)(bk0 + k0) * 256 + 128 + f] = (za0 + za1) * sinv[k0];
    out[(size_t)(bk0 + k1) * 256 + 128 + f] = (zb0 + zb1) * sinv[k1];

    for (int idx = tid; idx < 4 * DX_; idx += 256) {
        const int k = idx >> 7, ff = idx & 127;
        out[(size_t)(bk0 + k) * 256 + ff] = x0[(size_t)(bk0 + k) * DX_ + ff];
    }
}

// ---------------------------------------------------------------------------
extern "C" void kernel_launch(void* const* d_in, const int* in_sizes, int n_in,
                              void* d_out, int out_size)
{
    (void)in_sizes; (void)n_in; (void)out_size;
    const float* s2  = (const float*)d_in[0];
    const float* x0  = (const float*)d_in[1];
    const float* q   = (const float*)d_in[2];
    const float* w1  = (const float*)d_in[3];
    const float* b1  = (const float*)d_in[4];
    const float* w2  = (const float*)d_in[5];
    const float* hw1 = (const float*)d_in[7];
    const float* hb1 = (const float*)d_in[8];
    const float* hw2 = (const float*)d_in[9];
    const float* hb2 = (const float*)d_in[10];
    float* out = (float*)d_out;

    float *preq, *C, *hs, *base;
    __nv_bfloat16 *Ahi, *Alo, *Whi, *Wlo;
    cudaGetSymbolAddress((void**)&preq, g_preq);
    cudaGetSymbolAddress((void**)&C,    g_C);
    cudaGetSymbolAddress((void**)&hs,   g_hs);
    cudaGetSymbolAddress((void**)&base, g_base);
    cudaGetSymbolAddress((void**)&Ahi,  g_Ahi);
    cudaGetSymbolAddress((void**)&Alo,  g_Alo);
    cudaGetSymbolAddress((void**)&Whi,  g_Whi);
    cudaGetSymbolAddress((void**)&Wlo,  g_Wlo);

    // P: bf16 hi/lo split of s2 and [w_s|hw1], + preq
    prep_k<<<672, 256>>>(s2, w1, hw1, q, Ahi, Alo, Whi, Wlo, preq);
    // L1: tensor-core bf16x3 GEMM -> C (relu+hb1 fused for cols>=256)
    k1_mma<<<128, 256>>>(Ahi, Alo, Whi, Wlo, hb1, C);
    // L2: hs + base
    k2<<<136, 256>>>(C, hw2, hb2, x0, w1, b1, preq, hs, base);
    // L3: fused attention + output (4k/block, float4 staging, 4 acc chains)
    att_k<<<288, 256>>>(C, base, hs, w2, x0, out);
}

// round 15
// speedup vs baseline: 1.0882x; 1.0498x over previous
#include <cuda_runtime.h>
#include <cuda_bf16.h>
#include <cstdint>
#include <math.h>

typedef unsigned int u32;

#define B_  32
#define M_  64
#define Kk_ 36
#define DS_ 512
#define DX_ 128
#define DQ_ 512
#define H_  256
#define ROWS_S 2048
#define ROWS_X 1152

// Scratch (allocation-free rule: __device__ globals)
__device__ __align__(16) float g_preq[B_*H_];
__device__ __align__(16) float g_C[ROWS_S*512];      // 0:256 pre_s (raw), 256:512 h1=relu(..+hb1)
__device__ __align__(16) float g_hs[ROWS_S*DX_];
__device__ __align__(16) float g_base[ROWS_X*H_];
__device__ __align__(16) __nv_bfloat16 g_Ahi[ROWS_S*512];
__device__ __align__(16) __nv_bfloat16 g_Alo[ROWS_S*512];
__device__ __align__(16) __nv_bfloat16 g_Whi[512*512];  // cols 0:256 w_s, 256:512 hw1
__device__ __align__(16) __nv_bfloat16 g_Wlo[512*512];

__device__ __forceinline__ void fma2(float2 &d, const float2 &a, const float2 &b) {
    asm("fma.rn.f32x2 %0, %1, %2, %0;"
        : "+l"(reinterpret_cast<unsigned long long&>(d))
        : "l"(reinterpret_cast<const unsigned long long&>(a)),
          "l"(reinterpret_cast<const unsigned long long&>(b)));
}

__device__ __forceinline__ u32 smem_addr_u32(const void* zp) {
    return (u32)__cvta_generic_to_shared(zp);
}
__device__ __forceinline__ void ld_sm_x4(u32* zr, u32 zaddr) {
    asm volatile("ldmatrix.sync.aligned.m8n8.x4.shared.b16 {%0,%1,%2,%3}, [%4];"
        : "=r"(zr[0]), "=r"(zr[1]), "=r"(zr[2]), "=r"(zr[3]) : "r"(zaddr));
}
__device__ __forceinline__ void ld_sm_x4_t(u32* zr, u32 zaddr) {
    asm volatile("ldmatrix.sync.aligned.m8n8.x4.trans.shared.b16 {%0,%1,%2,%3}, [%4];"
        : "=r"(zr[0]), "=r"(zr[1]), "=r"(zr[2]), "=r"(zr[3]) : "r"(zaddr));
}
__device__ __forceinline__ void mma16816(float* zc, const u32* za, u32 zb0, u32 zb1) {
    asm volatile("mma.sync.aligned.m16n8k16.row.col.f32.bf16.bf16.f32 "
        "{%0,%1,%2,%3},{%4,%5,%6,%7},{%8,%9},{%0,%1,%2,%3};"
        : "+f"(zc[0]), "+f"(zc[1]), "+f"(zc[2]), "+f"(zc[3])
        : "r"(za[0]), "r"(za[1]), "r"(za[2]), "r"(za[3]), "r"(zb0), "r"(zb1));
}

// ---------------------------------------------------------------------------
// prep: bx<512  : convert s2 -> (Ahi, Alo)
//       512..639: convert [w_s|hw1] -> (Whi,Wlo)
//       bx>=640 : preq[b] = q[b] @ w_q
// ---------------------------------------------------------------------------
__global__ void __launch_bounds__(256) prep_k(
    const float* __restrict__ s2, const float* __restrict__ w1,
    const float* __restrict__ hw1, const float* __restrict__ q,
    __nv_bfloat16* __restrict__ Ahi, __nv_bfloat16* __restrict__ Alo,
    __nv_bfloat16* __restrict__ Whi, __nv_bfloat16* __restrict__ Wlo,
    float* __restrict__ preq)
{
    const int ztid = threadIdx.x;
    const int zbx  = blockIdx.x;

    if (zbx < 512) {
        size_t zoff = ((size_t)zbx * 256 + ztid) * 8;
        float4 zva = *reinterpret_cast<const float4*>(s2 + zoff);
        float4 zvb = *reinterpret_cast<const float4*>(s2 + zoff + 4);
        float zv[8] = {zva.x,zva.y,zva.z,zva.w,zvb.x,zvb.y,zvb.z,zvb.w};
        __nv_bfloat16 zhi[8];
        __nv_bfloat16 zlo[8];
        #pragma unroll
        for (int zi = 0; zi < 8; zi++) {
            zhi[zi] = __float2bfloat16(zv[zi]);
            zlo[zi] = __float2bfloat16(zv[zi] - __bfloat162float(zhi[zi]));
        }
        *reinterpret_cast<uint4*>(Ahi + zoff) = *reinterpret_cast<uint4*>(zhi);
        *reinterpret_cast<uint4*>(Alo + zoff) = *reinterpret_cast<uint4*>(zlo);
        return;
    }
    if (zbx < 640) {
        size_t zoff = ((size_t)(zbx - 512) * 256 + ztid) * 8;
        const int zk = (int)(zoff >> 9);
        const int zn = (int)(zoff & 511);
        const float* zsrc = (zn < 256) ? (w1 + (size_t)zk*256 + zn)
                                       : (hw1 + (size_t)zk*256 + (zn - 256));
        float4 zva = *reinterpret_cast<const float4*>(zsrc);
        float4 zvb = *reinterpret_cast<const float4*>(zsrc + 4);
        float zv[8] = {zva.x,zva.y,zva.z,zva.w,zvb.x,zvb.y,zvb.z,zvb.w};
        __nv_bfloat16 zhi[8];
        __nv_bfloat16 zlo[8];
        #pragma unroll
        for (int zi = 0; zi < 8; zi++) {
            zhi[zi] = __float2bfloat16(zv[zi]);
            zlo[zi] = __float2bfloat16(zv[zi] - __bfloat162float(zhi[zi]));
        }
        *reinterpret_cast<uint4*>(Whi + zoff) = *reinterpret_cast<uint4*>(zhi);
        *reinterpret_cast<uint4*>(Wlo + zoff) = *reinterpret_cast<uint4*>(zlo);
        return;
    }
    __shared__ float zqs[DQ_];
    const int zb = zbx - 640;
    for (int zd = ztid; zd < DQ_; zd += 256) zqs[zd] = q[zb*DQ_ + zd];
    __syncthreads();
    const float* zwq = w1 + (size_t)(DS_ + DX_) * H_ + ztid;
    float zacc0 = 0.f;
    float zacc1 = 0.f;
    #pragma unroll 8
    for (int zd = 0; zd < DQ_; zd += 2) {
        zacc0 = fmaf(zqs[zd],   zwq[(size_t)zd*H_],     zacc0);
        zacc1 = fmaf(zqs[zd+1], zwq[(size_t)(zd+1)*H_], zacc1);
    }
    preq[zb*H_ + ztid] = zacc0 + zacc1;
}

// ---------------------------------------------------------------------------
// k1_mma v2: C[2048,512] = [ s2@w_s | relu(s2@hw1+hb1) ] via bf16x3 MMA.
//   64x64 tile, BK=32, 16 iterations, 256 blocks (full chip), 8 warps (2m x 4n,
//   warp tile 32x16). Double-buffered smem; A stride 40, B stride 72 elems.
// ---------------------------------------------------------------------------
__global__ void __launch_bounds__(256) k1_mma(
    const __nv_bfloat16* __restrict__ Ahi, const __nv_bfloat16* __restrict__ Alo,
    const __nv_bfloat16* __restrict__ Whi, const __nv_bfloat16* __restrict__ Wlo,
    const float* __restrict__ hb1, float* __restrict__ C)
{
    __shared__ __align__(16) __nv_bfloat16 zSAhi[2][64][40];
    __shared__ __align__(16) __nv_bfloat16 zSAlo[2][64][40];
    __shared__ __align__(16) __nv_bfloat16 zSBhi[2][32][72];
    __shared__ __align__(16) __nv_bfloat16 zSBlo[2][32][72];

    const int ztid  = threadIdx.x;
    const int zbx   = blockIdx.x;
    const int zbm   = zbx >> 3;
    const int zbn   = zbx & 7;
    const int zm0   = zbm * 64;
    const int zn0   = zbn * 64;
    const int zwarp = ztid >> 5;
    const int zlane = ztid & 31;
    const int zwm   = zwarp & 1;        // m: 2 warps
    const int zwn   = zwarp >> 1;       // n: 4 warps

    // global loaders: A 64x32 (row=tid>>2, seg=(tid&3)*8); B 32x64 (row=tid>>3, col=(tid&7)*8)
    const int zArow = ztid >> 2;
    const int zAseg = (ztid & 3) * 8;
    const __nv_bfloat16* zgAhi = Ahi + (size_t)(zm0 + zArow) * 512 + zAseg;
    const __nv_bfloat16* zgAlo = Alo + (size_t)(zm0 + zArow) * 512 + zAseg;
    const int zBrow = ztid >> 3;
    const int zBcol = (ztid & 7) * 8;
    const __nv_bfloat16* zgBhi = Whi + (size_t)zBrow * 512 + zn0 + zBcol;
    const __nv_bfloat16* zgBlo = Wlo + (size_t)zBrow * 512 + zn0 + zBcol;

    float zacc[2][2][4];
    #pragma unroll
    for (int zf = 0; zf < 2; zf++) {
        #pragma unroll
        for (int zg = 0; zg < 2; zg++) {
            #pragma unroll
            for (int ze = 0; ze < 4; ze++) zacc[zf][zg][ze] = 0.f;
        }
    }

    // ldmatrix base addresses (buffer 0, kk=0)
    u32 zAdrAhi[2];
    u32 zAdrAlo[2];
    u32 zAdrBhi;
    u32 zAdrBlo;
    {
        const int zquad = zlane >> 3;
        const int zr8   = zlane & 7;
        #pragma unroll
        for (int zf = 0; zf < 2; zf++) {
            const int zrr = zwm*32 + zf*16 + (zquad & 1)*8 + zr8;
            const int zcc = (zquad >> 1) * 8;
            zAdrAhi[zf] = smem_addr_u32(&zSAhi[0][zrr][zcc]);
            zAdrAlo[zf] = smem_addr_u32(&zSAlo[0][zrr][zcc]);
        }
        const int zkr = (zquad & 1)*8 + zr8;
        const int znc = zwn*16 + (zquad >> 1)*8;
        zAdrBhi = smem_addr_u32(&zSBhi[0][zkr][znc]);
        zAdrBlo = smem_addr_u32(&zSBlo[0][zkr][znc]);
    }
    const u32 zBufA = (u32)(64*40*2);    // bytes per A buffer
    const u32 zBufB = (u32)(32*72*2);    // bytes per B buffer
    const u32 zKkA  = 32;                // 16 elems * 2B within A row
    const u32 zKkB  = (u32)(16*72*2);    // 16 k-rows within B

    // prefetch tile 0
    uint4 zPfAhi = *reinterpret_cast<const uint4*>(zgAhi);
    uint4 zPfAlo = *reinterpret_cast<const uint4*>(zgAlo);
    uint4 zPfBhi = *reinterpret_cast<const uint4*>(zgBhi);
    uint4 zPfBlo = *reinterpret_cast<const uint4*>(zgBlo);
    *reinterpret_cast<uint4*>(&zSAhi[0][zArow][zAseg]) = zPfAhi;
    *reinterpret_cast<uint4*>(&zSAlo[0][zArow][zAseg]) = zPfAlo;
    *reinterpret_cast<uint4*>(&zSBhi[0][zBrow][zBcol]) = zPfBhi;
    *reinterpret_cast<uint4*>(&zSBlo[0][zBrow][zBcol]) = zPfBlo;
    __syncthreads();

    #pragma unroll 1
    for (int zkt = 0; zkt < 16; zkt++) {
        const int zbuf = zkt & 1;
        if (zkt < 15) {
            zPfAhi = *reinterpret_cast<const uint4*>(zgAhi + (zkt+1)*32);
            zPfAlo = *reinterpret_cast<const uint4*>(zgAlo + (zkt+1)*32);
            zPfBhi = *reinterpret_cast<const uint4*>(zgBhi + (size_t)(zkt+1)*32*512);
            zPfBlo = *reinterpret_cast<const uint4*>(zgBlo + (size_t)(zkt+1)*32*512);
        }
        #pragma unroll
        for (int zkk = 0; zkk < 2; zkk++) {
            u32 zFAhi[2][4];
            u32 zFAlo[2][4];
            u32 zFBhi[4];
            u32 zFBlo[4];
            #pragma unroll
            for (int zf = 0; zf < 2; zf++) {
                ld_sm_x4(zFAhi[zf], zAdrAhi[zf] + zbuf*zBufA + zkk*zKkA);
                ld_sm_x4(zFAlo[zf], zAdrAlo[zf] + zbuf*zBufA + zkk*zKkA);
            }
            ld_sm_x4_t(zFBhi, zAdrBhi + zbuf*zBufB + zkk*zKkB);
            ld_sm_x4_t(zFBlo, zAdrBlo + zbuf*zBufB + zkk*zKkB);
            #pragma unroll
            for (int zf = 0; zf < 2; zf++) {
                #pragma unroll
                for (int zg = 0; zg < 2; zg++) {
                    const int zs = zg * 2;
                    mma16816(zacc[zf][zg], zFAhi[zf], zFBhi[zs], zFBhi[zs+1]);
                    mma16816(zacc[zf][zg], zFAhi[zf], zFBlo[zs], zFBlo[zs+1]);
                    mma16816(zacc[zf][zg], zFAlo[zf], zFBhi[zs], zFBhi[zs+1]);
                }
            }
        }
        if (zkt < 15) {
            const int znb = zbuf ^ 1;
            *reinterpret_cast<uint4*>(&zSAhi[znb][zArow][zAseg]) = zPfAhi;
            *reinterpret_cast<uint4*>(&zSAlo[znb][zArow][zAseg]) = zPfAlo;
            *reinterpret_cast<uint4*>(&zSBhi[znb][zBrow][zBcol]) = zPfBhi;
            *reinterpret_cast<uint4*>(&zSBlo[znb][zBrow][zBcol]) = zPfBlo;
        }
        __syncthreads();
    }

    // epilogue
    const bool zRelu = (zn0 >= 256);
    #pragma unroll
    for (int zf = 0; zf < 2; zf++) {
        #pragma unroll
        for (int zg = 0; zg < 2; zg++) {
            const int zrow = zm0 + zwm*32 + zf*16 + (zlane >> 2);
            const int zcol = zn0 + zwn*16 + zg*8 + (zlane & 3)*2;
            float2 zv0 = make_float2(zacc[zf][zg][0], zacc[zf][zg][1]);
            float2 zv1 = make_float2(zacc[zf][zg][2], zacc[zf][zg][3]);
            if (zRelu) {
                float2 zbb = *reinterpret_cast<const float2*>(&hb1[zcol - 256]);
                zv0.x = fmaxf(zv0.x + zbb.x, 0.f); zv0.y = fmaxf(zv0.y + zbb.y, 0.f);
                zv1.x = fmaxf(zv1.x + zbb.x, 0.f); zv1.y = fmaxf(zv1.y + zbb.y, 0.f);
            }
            *reinterpret_cast<float2*>(&C[(size_t)zrow * 512 + zcol])       = zv0;
            *reinterpret_cast<float2*>(&C[(size_t)(zrow + 8) * 512 + zcol]) = zv1;
        }
    }
}

// ---------------------------------------------------------------------------
// k2: bx<64 : hs[2048,128] = h1 @ hw2 + hb2      (64x64 tiles, K=256)
//     bx>=64: base[1152,256] = x0@w_x + preq[row/36] + b1  (64x64, K=128)
// ---------------------------------------------------------------------------
__global__ void __launch_bounds__(256) k2(
    const float* __restrict__ C, const float* __restrict__ hw2,
    const float* __restrict__ hb2, const float* __restrict__ x0,
    const float* __restrict__ w1, const float* __restrict__ b1,
    const float* __restrict__ preq,
    float* __restrict__ hs, float* __restrict__ base)
{
    __shared__ float As[2][16][68];
    __shared__ float Bs[2][16][64];
    const int tid = threadIdx.x;
    const int bx  = blockIdx.x;

    const float* A; const float* Bp; int lda, ldb, nt, m0, n0, mode;
    if (bx < 64) {
        mode = 0; const int tm = bx >> 1, tn = bx & 1;
        m0 = tm*64; n0 = tn*64;
        A = C + 256; lda = 512; Bp = hw2; ldb = 128; nt = 256/16;
    } else {
        mode = 1; const int bb = bx - 64; const int tm = bb >> 2, tn = bb & 3;
        m0 = tm*64; n0 = tn*64;
        A = x0; lda = 128; Bp = w1 + (size_t)DS_*H_; ldb = 256; nt = 128/16;
    }

    const int tx = tid & 15, ty = tid >> 4;
    const int ar = tid >> 2;
    const int ac = (tid & 3) << 2;
    const int bkr = tid >> 4;
    const int bn4 = (tid & 15) << 2;

    const float* Ag = A  + (size_t)(m0 + ar) * lda + ac;
    const float* Bg = Bp + (size_t)bkr * ldb + n0 + bn4;

    float2 acc[2][4];
    #pragma unroll
    for (int i = 0; i < 2; i++) {
        #pragma unroll
        for (int j = 0; j < 4; j++) acc[i][j] = make_float2(0.f, 0.f);
    }

    float4 av = *reinterpret_cast<const float4*>(Ag);
    float4 bv = *reinterpret_cast<const float4*>(Bg);
    As[0][ac+0][ar] = av.x; As[0][ac+1][ar] = av.y;
    As[0][ac+2][ar] = av.z; As[0][ac+3][ar] = av.w;
    *reinterpret_cast<float4*>(&Bs[0][bkr][bn4]) = bv;
    __syncthreads();

    #pragma unroll 1
    for (int kt = 0; kt < nt; kt++) {
        const int buf = kt & 1;
        if (kt + 1 < nt) {
            av = *reinterpret_cast<const float4*>(Ag + (kt+1)*16);
            bv = *reinterpret_cast<const float4*>(Bg + (size_t)(kt+1)*16*ldb);
        }
        #pragma unroll
        for (int kk = 0; kk < 16; kk++) {
            float4 a4 = *reinterpret_cast<const float4*>(&As[buf][kk][ty*4]);
            float4 b4 = *reinterpret_cast<const float4*>(&Bs[buf][kk][tx*4]);
            float2 a2v[2] = {{a4.x,a4.y},{a4.z,a4.w}};
            float2 bd[4]  = {{b4.x,b4.x},{b4.y,b4.y},{b4.z,b4.z},{b4.w,b4.w}};
            #pragma unroll
            for (int i = 0; i < 2; i++) {
                #pragma unroll
                for (int j = 0; j < 4; j++)
                    fma2(acc[i][j], a2v[i], bd[j]);
            }
        }
        if (kt + 1 < nt) {
            const int nb = buf ^ 1;
            As[nb][ac+0][ar] = av.x; As[nb][ac+1][ar] = av.y;
            As[nb][ac+2][ar] = av.z; As[nb][ac+3][ar] = av.w;
            *reinterpret_cast<float4*>(&Bs[nb][bkr][bn4]) = bv;
        }
        __syncthreads();
    }

    if (mode == 0) {
        float4 bb = *reinterpret_cast<const float4*>(&hb2[n0 + tx*4]);
        float* Or = hs + (size_t)(m0 + ty*4) * DX_ + n0 + tx*4;
        #pragma unroll
        for (int i = 0; i < 2; i++) {
            float4 lo = make_float4(acc[i][0].x+bb.x, acc[i][1].x+bb.y, acc[i][2].x+bb.z, acc[i][3].x+bb.w);
            float4 hi = make_float4(acc[i][0].y+bb.x, acc[i][1].y+bb.y, acc[i][2].y+bb.z, acc[i][3].y+bb.w);
            *reinterpret_cast<float4*>(Or + (size_t)(2*i  )*DX_) = lo;
            *reinterpret_cast<float4*>(Or + (size_t)(2*i+1)*DX_) = hi;
        }
    } else {
        float4 bb = *reinterpret_cast<const float4*>(&b1[n0 + tx*4]);
        #pragma unroll
        for (int i = 0; i < 2; i++) {
            const int r0 = m0 + ty*4 + 2*i;
            float4 p0 = *reinterpret_cast<const float4*>(&preq[(r0   /Kk_)*H_ + n0 + tx*4]);
            float4 p1 = *reinterpret_cast<const float4*>(&preq[((r0+1)/Kk_)*H_ + n0 + tx*4]);
            float4 lo = make_float4(acc[i][0].x+bb.x+p0.x, acc[i][1].x+bb.y+p0.y,
                                    acc[i][2].x+bb.z+p0.z, acc[i][3].x+bb.w+p0.w);
            float4 hi = make_float4(acc[i][0].y+bb.x+p1.x, acc[i][1].y+bb.y+p1.y,
                                    acc[i][2].y+bb.z+p1.z, acc[i][3].y+bb.w+p1.w);
            *reinterpret_cast<float4*>(&base[(size_t)(r0  )*H_ + n0 + tx*4]) = lo;
            *reinterpret_cast<float4*>(&base[(size_t)(r0+1)*H_ + n0 + tx*4]) = hi;
        }
    }
}

// ---------------------------------------------------------------------------
// att v4: 4 k per block (288 blocks), smem-staged pre_s at stride 68,
//   16 x LDS.128 inner loop with 4 independent accumulator chains.
// ---------------------------------------------------------------------------
__global__ void __launch_bounds__(256) att_k(
    const float* __restrict__ Cmat, const float* __restrict__ base,
    const float* __restrict__ hsm, const float* __restrict__ w2,
    const float* __restrict__ x0, float* __restrict__ out)
{
    const int b  = blockIdx.x / 9;
    const int kg = blockIdx.x % 9;
    const int bk0 = b * Kk_ + kg * 4;
    const int tid = threadIdx.x;
    const int warp = tid >> 5, lane = tid & 31;

    __shared__ __align__(16) float sbuf[64*68];
    __shared__ float base_s[4][H_];
    __shared__ float w2s[H_];
    __shared__ float lgt[4][M_];
    __shared__ float ew[4][M_];
    __shared__ float sinv[4];

    for (int idx = tid; idx < 4*H_; idx += 256)
        base_s[idx >> 8][idx & 255] = base[(size_t)(bk0 + (idx >> 8)) * H_ + (idx & 255)];
    w2s[tid] = w2[tid];

    const int km = tid >> 6;
    const int mm = tid & 63;
    const float* pres = Cmat + (size_t)(b * M_) * 512;

    float a0 = 0.f, a1 = 0.f, a2 = 0.f, a3 = 0.f;
    #pragma unroll 1
    for (int hc = 0; hc < 4; hc++) {
        __syncthreads();
        #pragma unroll
        for (int i = 0; i < 4; i++) {
            const int fi  = tid + i * 256;
            const int row = fi >> 4;
            const int c4  = (fi & 15) * 4;
            float4 v = *reinterpret_cast<const float4*>(pres + (size_t)row * 512 + hc * 64 + c4);
            *reinterpret_cast<float4*>(&sbuf[row * 68 + c4]) = v;
        }
        __syncthreads();
        const float* srow = &sbuf[mm * 68];
        const float* bs   = &base_s[km][hc * 64];
        const float* ws   = &w2s[hc * 64];
        #pragma unroll
        for (int jj = 0; jj < 16; jj++) {
            float4 v  = *reinterpret_cast<const float4*>(srow + jj * 4);
            float4 bb = *reinterpret_cast<const float4*>(bs + jj * 4);
            float4 ww = *reinterpret_cast<const float4*>(ws + jj * 4);
            a0 = fmaf(fmaxf(v.x + bb.x, 0.f), ww.x, a0);
            a1 = fmaf(fmaxf(v.y + bb.y, 0.f), ww.y, a1);
            a2 = fmaf(fmaxf(v.z + bb.z, 0.f), ww.z, a2);
            a3 = fmaf(fmaxf(v.w + bb.w, 0.f), ww.w, a3);
        }
    }
    lgt[km][mm] = (a0 + a1) + (a2 + a3);
    __syncthreads();

    if (warp < 4) {
        const int k = warp;
        float l0 = lgt[k][lane], l1 = lgt[k][lane + 32];
        float mx = fmaxf(l0, l1);
        #pragma unroll
        for (int off = 16; off; off >>= 1)
            mx = fmaxf(mx, __shfl_xor_sync(0xffffffffu, mx, off));
        float e0 = expf(l0 - mx), e1 = expf(l1 - mx);
        float s = e0 + e1;
        #pragma unroll
        for (int off = 16; off; off >>= 1)
            s += __shfl_xor_sync(0xffffffffu, s, off);
        ew[k][lane] = e0; ew[k][lane + 32] = e1;
        if (lane == 0) sinv[k] = 1.f / s;
    }

    const int f  = tid & 127;
    const int kp = tid >> 7;
    const int k0 = kp * 2, k1 = k0 + 1;
    float za0 = 0.f, za1 = 0.f, zb0 = 0.f, zb1 = 0.f;
    const float* hsb = hsm + (size_t)(b * M_) * DX_;
    #pragma unroll 1
    for (int mc = 0; mc < 2; mc++) {
        __syncthreads();
        #pragma unroll
        for (int i = 0; i < 4; i++) {
            const int fi  = tid + i * 256;
            const int row = fi >> 5;
            const int c4  = (fi & 31) * 4;
            float4 v = *reinterpret_cast<const float4*>(hsb + (size_t)(mc * 32 + row) * DX_ + c4);
            float* d = &sbuf[row * 130 + c4];
            d[0] = v.x; d[1] = v.y; d[2] = v.z; d[3] = v.w;
        }
        __syncthreads();
        const float* e0p = &ew[k0][mc * 32];
        const float* e1p = &ew[k1][mc * 32];
        #pragma unroll 8
        for (int m = 0; m < 32; m += 2) {
            const float v0 = sbuf[m * 130 + f];
            const float v1 = sbuf[(m + 1) * 130 + f];
            za0 = fmaf(e0p[m],     v0, za0);
            za1 = fmaf(e0p[m + 1], v1, za1);
            zb0 = fmaf(e1p[m],     v0, zb0);
            zb1 = fmaf(e1p[m + 1], v1, zb1);
        }
    }
    out[(size_t)(bk0 + k0) * 256 + 128 + f] = (za0 + za1) * sinv[k0];
    out[(size_t)(bk0 + k1) * 256 + 128 + f] = (zb0 + zb1) * sinv[k1];

    for (int idx = tid; idx < 4 * DX_; idx += 256) {
        const int k = idx >> 7, ff = idx & 127;
        out[(size_t)(bk0 + k) * 256 + ff] = x0[(size_t)(bk0 + k) * DX_ + ff];
    }
}

// ---------------------------------------------------------------------------
extern "C" void kernel_launch(void* const* d_in, const int* in_sizes, int n_in,
                              void* d_out, int out_size)
{
    (void)in_sizes; (void)n_in; (void)out_size;
    const float* s2  = (const float*)d_in[0];
    const float* x0  = (const float*)d_in[1];
    const float* q   = (const float*)d_in[2];
    const float* w1  = (const float*)d_in[3];
    const float* b1  = (const float*)d_in[4];
    const float* w2  = (const float*)d_in[5];
    const float* hw1 = (const float*)d_in[7];
    const float* hb1 = (const float*)d_in[8];
    const float* hw2 = (const float*)d_in[9];
    const float* hb2 = (const float*)d_in[10];
    float* out = (float*)d_out;

    float *preq, *C, *hs, *base;
    __nv_bfloat16 *Ahi, *Alo, *Whi, *Wlo;
    cudaGetSymbolAddress((void**)&preq, g_preq);
    cudaGetSymbolAddress((void**)&C,    g_C);
    cudaGetSymbolAddress((void**)&hs,   g_hs);
    cudaGetSymbolAddress((void**)&base, g_base);
    cudaGetSymbolAddress((void**)&Ahi,  g_Ahi);
    cudaGetSymbolAddress((void**)&Alo,  g_Alo);
    cudaGetSymbolAddress((void**)&Whi,  g_Whi);
    cudaGetSymbolAddress((void**)&Wlo,  g_Wlo);

    // P: bf16 hi/lo split of s2 and [w_s|hw1], + preq
    prep_k<<<672, 256>>>(s2, w1, hw1, q, Ahi, Alo, Whi, Wlo, preq);
    // L1: tensor-core bf16x3 GEMM -> C (64x64 tiles, 256 blocks, BK=32)
    k1_mma<<<256, 256>>>(Ahi, Alo, Whi, Wlo, hb1, C);
    // L2: hs + base
    k2<<<136, 256>>>(C, hw2, hb2, x0, w1, b1, preq, hs, base);
    // L3: fused attention + output
    att_k<<<288, 256>>>(C, base, hs, w2, x0, out);
}

// round 16
// speedup vs baseline: 1.1177x; 1.0271x over previous
#include <cuda_runtime.h>
#include <cuda_bf16.h>
#include <cstdint>
#include <math.h>

typedef unsigned int u32;

#define B_  32
#define M_  64
#define Kk_ 36
#define DS_ 512
#define DX_ 128
#define DQ_ 512
#define H_  256
#define ROWS_S 2048
#define ROWS_X 1152

// Scratch (allocation-free rule: __device__ globals)
__device__ __align__(16) float g_preq[B_*H_];
__device__ __align__(16) float g_C[ROWS_S*512];      // 0:256 pre_s (raw), 256:512 h1=relu(..+hb1)
__device__ __align__(16) float g_hs[ROWS_S*DX_];
__device__ __align__(16) float g_base[ROWS_X*H_];
__device__ __align__(16) __nv_bfloat16 g_Ahi[ROWS_S*512];
__device__ __align__(16) __nv_bfloat16 g_Alo[ROWS_S*512];
__device__ __align__(16) __nv_bfloat16 g_Whi[512*512];  // cols 0:256 w_s, 256:512 hw1
__device__ __align__(16) __nv_bfloat16 g_Wlo[512*512];

__device__ __forceinline__ void fma2(float2 &d, const float2 &a, const float2 &b) {
    asm("fma.rn.f32x2 %0, %1, %2, %0;"
        : "+l"(reinterpret_cast<unsigned long long&>(d))
        : "l"(reinterpret_cast<const unsigned long long&>(a)),
          "l"(reinterpret_cast<const unsigned long long&>(b)));
}

__device__ __forceinline__ u32 smem_addr_u32(const void* zp) {
    return (u32)__cvta_generic_to_shared(zp);
}
__device__ __forceinline__ void ld_sm_x4(u32* zr, u32 zaddr) {
    asm volatile("ldmatrix.sync.aligned.m8n8.x4.shared.b16 {%0,%1,%2,%3}, [%4];"
        : "=r"(zr[0]), "=r"(zr[1]), "=r"(zr[2]), "=r"(zr[3]) : "r"(zaddr));
}
__device__ __forceinline__ void ld_sm_x4_t(u32* zr, u32 zaddr) {
    asm volatile("ldmatrix.sync.aligned.m8n8.x4.trans.shared.b16 {%0,%1,%2,%3}, [%4];"
        : "=r"(zr[0]), "=r"(zr[1]), "=r"(zr[2]), "=r"(zr[3]) : "r"(zaddr));
}
__device__ __forceinline__ void mma16816(float* zc, const u32* za, u32 zb0, u32 zb1) {
    asm volatile("mma.sync.aligned.m16n8k16.row.col.f32.bf16.bf16.f32 "
        "{%0,%1,%2,%3},{%4,%5,%6,%7},{%8,%9},{%0,%1,%2,%3};"
        : "+f"(zc[0]), "+f"(zc[1]), "+f"(zc[2]), "+f"(zc[3])
        : "r"(za[0]), "r"(za[1]), "r"(za[2]), "r"(za[3]), "r"(zb0), "r"(zb1));
}

// ---------------------------------------------------------------------------
// prep: bx<512  : convert s2 -> (Ahi, Alo)
//       512..639: convert [w_s|hw1] -> (Whi,Wlo)
//       bx>=640 : preq[b] = q[b] @ w_q
// ---------------------------------------------------------------------------
__global__ void __launch_bounds__(256) prep_k(
    const float* __restrict__ s2, const float* __restrict__ w1,
    const float* __restrict__ hw1, const float* __restrict__ q,
    __nv_bfloat16* __restrict__ Ahi, __nv_bfloat16* __restrict__ Alo,
    __nv_bfloat16* __restrict__ Whi, __nv_bfloat16* __restrict__ Wlo,
    float* __restrict__ preq)
{
    const int ztid = threadIdx.x;
    const int zbx  = blockIdx.x;

    if (zbx < 512) {
        size_t zoff = ((size_t)zbx * 256 + ztid) * 8;
        float4 zva = *reinterpret_cast<const float4*>(s2 + zoff);
        float4 zvb = *reinterpret_cast<const float4*>(s2 + zoff + 4);
        float zv[8] = {zva.x,zva.y,zva.z,zva.w,zvb.x,zvb.y,zvb.z,zvb.w};
        __nv_bfloat16 zhi[8];
        __nv_bfloat16 zlo[8];
        #pragma unroll
        for (int zi = 0; zi < 8; zi++) {
            zhi[zi] = __float2bfloat16(zv[zi]);
            zlo[zi] = __float2bfloat16(zv[zi] - __bfloat162float(zhi[zi]));
        }
        *reinterpret_cast<uint4*>(Ahi + zoff) = *reinterpret_cast<uint4*>(zhi);
        *reinterpret_cast<uint4*>(Alo + zoff) = *reinterpret_cast<uint4*>(zlo);
        return;
    }
    if (zbx < 640) {
        size_t zoff = ((size_t)(zbx - 512) * 256 + ztid) * 8;
        const int zk = (int)(zoff >> 9);
        const int zn = (int)(zoff & 511);
        const float* zsrc = (zn < 256) ? (w1 + (size_t)zk*256 + zn)
                                       : (hw1 + (size_t)zk*256 + (zn - 256));
        float4 zva = *reinterpret_cast<const float4*>(zsrc);
        float4 zvb = *reinterpret_cast<const float4*>(zsrc + 4);
        float zv[8] = {zva.x,zva.y,zva.z,zva.w,zvb.x,zvb.y,zvb.z,zvb.w};
        __nv_bfloat16 zhi[8];
        __nv_bfloat16 zlo[8];
        #pragma unroll
        for (int zi = 0; zi < 8; zi++) {
            zhi[zi] = __float2bfloat16(zv[zi]);
            zlo[zi] = __float2bfloat16(zv[zi] - __bfloat162float(zhi[zi]));
        }
        *reinterpret_cast<uint4*>(Whi + zoff) = *reinterpret_cast<uint4*>(zhi);
        *reinterpret_cast<uint4*>(Wlo + zoff) = *reinterpret_cast<uint4*>(zlo);
        return;
    }
    __shared__ float zqs[DQ_];
    const int zb = zbx - 640;
    for (int zd = ztid; zd < DQ_; zd += 256) zqs[zd] = q[zb*DQ_ + zd];
    __syncthreads();
    const float* zwq = w1 + (size_t)(DS_ + DX_) * H_ + ztid;
    float zacc0 = 0.f;
    float zacc1 = 0.f;
    #pragma unroll 8
    for (int zd = 0; zd < DQ_; zd += 2) {
        zacc0 = fmaf(zqs[zd],   zwq[(size_t)zd*H_],     zacc0);
        zacc1 = fmaf(zqs[zd+1], zwq[(size_t)(zd+1)*H_], zacc1);
    }
    preq[zb*H_ + ztid] = zacc0 + zacc1;
}

// ---------------------------------------------------------------------------
// k1_mma v2: C[2048,512] = [ s2@w_s | relu(s2@hw1+hb1) ] via bf16x3 MMA.
//   64x64 tile, BK=32, 16 iterations, 256 blocks, 8 warps (2m x 4n).
// ---------------------------------------------------------------------------
__global__ void __launch_bounds__(256) k1_mma(
    const __nv_bfloat16* __restrict__ Ahi, const __nv_bfloat16* __restrict__ Alo,
    const __nv_bfloat16* __restrict__ Whi, const __nv_bfloat16* __restrict__ Wlo,
    const float* __restrict__ hb1, float* __restrict__ C)
{
    __shared__ __align__(16) __nv_bfloat16 zSAhi[2][64][40];
    __shared__ __align__(16) __nv_bfloat16 zSAlo[2][64][40];
    __shared__ __align__(16) __nv_bfloat16 zSBhi[2][32][72];
    __shared__ __align__(16) __nv_bfloat16 zSBlo[2][32][72];

    const int ztid  = threadIdx.x;
    const int zbx   = blockIdx.x;
    const int zbm   = zbx >> 3;
    const int zbn   = zbx & 7;
    const int zm0   = zbm * 64;
    const int zn0   = zbn * 64;
    const int zwarp = ztid >> 5;
    const int zlane = ztid & 31;
    const int zwm   = zwarp & 1;
    const int zwn   = zwarp >> 1;

    const int zArow = ztid >> 2;
    const int zAseg = (ztid & 3) * 8;
    const __nv_bfloat16* zgAhi = Ahi + (size_t)(zm0 + zArow) * 512 + zAseg;
    const __nv_bfloat16* zgAlo = Alo + (size_t)(zm0 + zArow) * 512 + zAseg;
    const int zBrow = ztid >> 3;
    const int zBcol = (ztid & 7) * 8;
    const __nv_bfloat16* zgBhi = Whi + (size_t)zBrow * 512 + zn0 + zBcol;
    const __nv_bfloat16* zgBlo = Wlo + (size_t)zBrow * 512 + zn0 + zBcol;

    float zacc[2][2][4];
    #pragma unroll
    for (int zf = 0; zf < 2; zf++) {
        #pragma unroll
        for (int zg = 0; zg < 2; zg++) {
            #pragma unroll
            for (int ze = 0; ze < 4; ze++) zacc[zf][zg][ze] = 0.f;
        }
    }

    u32 zAdrAhi[2];
    u32 zAdrAlo[2];
    u32 zAdrBhi;
    u32 zAdrBlo;
    {
        const int zquad = zlane >> 3;
        const int zr8   = zlane & 7;
        #pragma unroll
        for (int zf = 0; zf < 2; zf++) {
            const int zrr = zwm*32 + zf*16 + (zquad & 1)*8 + zr8;
            const int zcc = (zquad >> 1) * 8;
            zAdrAhi[zf] = smem_addr_u32(&zSAhi[0][zrr][zcc]);
            zAdrAlo[zf] = smem_addr_u32(&zSAlo[0][zrr][zcc]);
        }
        const int zkr = (zquad & 1)*8 + zr8;
        const int znc = zwn*16 + (zquad >> 1)*8;
        zAdrBhi = smem_addr_u32(&zSBhi[0][zkr][znc]);
        zAdrBlo = smem_addr_u32(&zSBlo[0][zkr][znc]);
    }
    const u32 zBufA = (u32)(64*40*2);
    const u32 zBufB = (u32)(32*72*2);
    const u32 zKkA  = 32;
    const u32 zKkB  = (u32)(16*72*2);

    uint4 zPfAhi = *reinterpret_cast<const uint4*>(zgAhi);
    uint4 zPfAlo = *reinterpret_cast<const uint4*>(zgAlo);
    uint4 zPfBhi = *reinterpret_cast<const uint4*>(zgBhi);
    uint4 zPfBlo = *reinterpret_cast<const uint4*>(zgBlo);
    *reinterpret_cast<uint4*>(&zSAhi[0][zArow][zAseg]) = zPfAhi;
    *reinterpret_cast<uint4*>(&zSAlo[0][zArow][zAseg]) = zPfAlo;
    *reinterpret_cast<uint4*>(&zSBhi[0][zBrow][zBcol]) = zPfBhi;
    *reinterpret_cast<uint4*>(&zSBlo[0][zBrow][zBcol]) = zPfBlo;
    __syncthreads();

    #pragma unroll 1
    for (int zkt = 0; zkt < 16; zkt++) {
        const int zbuf = zkt & 1;
        if (zkt < 15) {
            zPfAhi = *reinterpret_cast<const uint4*>(zgAhi + (zkt+1)*32);
            zPfAlo = *reinterpret_cast<const uint4*>(zgAlo + (zkt+1)*32);
            zPfBhi = *reinterpret_cast<const uint4*>(zgBhi + (size_t)(zkt+1)*32*512);
            zPfBlo = *reinterpret_cast<const uint4*>(zgBlo + (size_t)(zkt+1)*32*512);
        }
        #pragma unroll
        for (int zkk = 0; zkk < 2; zkk++) {
            u32 zFAhi[2][4];
            u32 zFAlo[2][4];
            u32 zFBhi[4];
            u32 zFBlo[4];
            #pragma unroll
            for (int zf = 0; zf < 2; zf++) {
                ld_sm_x4(zFAhi[zf], zAdrAhi[zf] + zbuf*zBufA + zkk*zKkA);
                ld_sm_x4(zFAlo[zf], zAdrAlo[zf] + zbuf*zBufA + zkk*zKkA);
            }
            ld_sm_x4_t(zFBhi, zAdrBhi + zbuf*zBufB + zkk*zKkB);
            ld_sm_x4_t(zFBlo, zAdrBlo + zbuf*zBufB + zkk*zKkB);
            #pragma unroll
            for (int zf = 0; zf < 2; zf++) {
                #pragma unroll
                for (int zg = 0; zg < 2; zg++) {
                    const int zs = zg * 2;
                    mma16816(zacc[zf][zg], zFAhi[zf], zFBhi[zs], zFBhi[zs+1]);
                    mma16816(zacc[zf][zg], zFAhi[zf], zFBlo[zs], zFBlo[zs+1]);
                    mma16816(zacc[zf][zg], zFAlo[zf], zFBhi[zs], zFBhi[zs+1]);
                }
            }
        }
        if (zkt < 15) {
            const int znb = zbuf ^ 1;
            *reinterpret_cast<uint4*>(&zSAhi[znb][zArow][zAseg]) = zPfAhi;
            *reinterpret_cast<uint4*>(&zSAlo[znb][zArow][zAseg]) = zPfAlo;
            *reinterpret_cast<uint4*>(&zSBhi[znb][zBrow][zBcol]) = zPfBhi;
            *reinterpret_cast<uint4*>(&zSBlo[znb][zBrow][zBcol]) = zPfBlo;
        }
        __syncthreads();
    }

    const bool zRelu = (zn0 >= 256);
    #pragma unroll
    for (int zf = 0; zf < 2; zf++) {
        #pragma unroll
        for (int zg = 0; zg < 2; zg++) {
            const int zrow = zm0 + zwm*32 + zf*16 + (zlane >> 2);
            const int zcol = zn0 + zwn*16 + zg*8 + (zlane & 3)*2;
            float2 zv0 = make_float2(zacc[zf][zg][0], zacc[zf][zg][1]);
            float2 zv1 = make_float2(zacc[zf][zg][2], zacc[zf][zg][3]);
            if (zRelu) {
                float2 zbb = *reinterpret_cast<const float2*>(&hb1[zcol - 256]);
                zv0.x = fmaxf(zv0.x + zbb.x, 0.f); zv0.y = fmaxf(zv0.y + zbb.y, 0.f);
                zv1.x = fmaxf(zv1.x + zbb.x, 0.f); zv1.y = fmaxf(zv1.y + zbb.y, 0.f);
            }
            *reinterpret_cast<float2*>(&C[(size_t)zrow * 512 + zcol])       = zv0;
            *reinterpret_cast<float2*>(&C[(size_t)(zrow + 8) * 512 + zcol]) = zv1;
        }
    }
}

// ---------------------------------------------------------------------------
// k2: bx<64 : hs[2048,128] = h1 @ hw2 + hb2      (64x64 tiles, K=256)
//     bx>=64: base[1152,256] = x0@w_x + preq[row/36] + b1  (64x64, K=128)
// ---------------------------------------------------------------------------
__global__ void __launch_bounds__(256) k2(
    const float* __restrict__ C, const float* __restrict__ hw2,
    const float* __restrict__ hb2, const float* __restrict__ x0,
    const float* __restrict__ w1, const float* __restrict__ b1,
    const float* __restrict__ preq,
    float* __restrict__ hs, float* __restrict__ base)
{
    __shared__ float As[2][16][68];
    __shared__ float Bs[2][16][64];
    const int tid = threadIdx.x;
    const int bx  = blockIdx.x;

    const float* A; const float* Bp; int lda, ldb, nt, m0, n0, mode;
    if (bx < 64) {
        mode = 0; const int tm = bx >> 1, tn = bx & 1;
        m0 = tm*64; n0 = tn*64;
        A = C + 256; lda = 512; Bp = hw2; ldb = 128; nt = 256/16;
    } else {
        mode = 1; const int bb = bx - 64; const int tm = bb >> 2, tn = bb & 3;
        m0 = tm*64; n0 = tn*64;
        A = x0; lda = 128; Bp = w1 + (size_t)DS_*H_; ldb = 256; nt = 128/16;
    }

    const int tx = tid & 15, ty = tid >> 4;
    const int ar = tid >> 2;
    const int ac = (tid & 3) << 2;
    const int bkr = tid >> 4;
    const int bn4 = (tid & 15) << 2;

    const float* Ag = A  + (size_t)(m0 + ar) * lda + ac;
    const float* Bg = Bp + (size_t)bkr * ldb + n0 + bn4;

    float2 acc[2][4];
    #pragma unroll
    for (int i = 0; i < 2; i++) {
        #pragma unroll
        for (int j = 0; j < 4; j++) acc[i][j] = make_float2(0.f, 0.f);
    }

    float4 av = *reinterpret_cast<const float4*>(Ag);
    float4 bv = *reinterpret_cast<const float4*>(Bg);
    As[0][ac+0][ar] = av.x; As[0][ac+1][ar] = av.y;
    As[0][ac+2][ar] = av.z; As[0][ac+3][ar] = av.w;
    *reinterpret_cast<float4*>(&Bs[0][bkr][bn4]) = bv;
    __syncthreads();

    #pragma unroll 1
    for (int kt = 0; kt < nt; kt++) {
        const int buf = kt & 1;
        if (kt + 1 < nt) {
            av = *reinterpret_cast<const float4*>(Ag + (kt+1)*16);
            bv = *reinterpret_cast<const float4*>(Bg + (size_t)(kt+1)*16*ldb);
        }
        #pragma unroll
        for (int kk = 0; kk < 16; kk++) {
            float4 a4 = *reinterpret_cast<const float4*>(&As[buf][kk][ty*4]);
            float4 b4 = *reinterpret_cast<const float4*>(&Bs[buf][kk][tx*4]);
            float2 a2v[2] = {{a4.x,a4.y},{a4.z,a4.w}};
            float2 bd[4]  = {{b4.x,b4.x},{b4.y,b4.y},{b4.z,b4.z},{b4.w,b4.w}};
            #pragma unroll
            for (int i = 0; i < 2; i++) {
                #pragma unroll
                for (int j = 0; j < 4; j++)
                    fma2(acc[i][j], a2v[i], bd[j]);
            }
        }
        if (kt + 1 < nt) {
            const int nb = buf ^ 1;
            As[nb][ac+0][ar] = av.x; As[nb][ac+1][ar] = av.y;
            As[nb][ac+2][ar] = av.z; As[nb][ac+3][ar] = av.w;
            *reinterpret_cast<float4*>(&Bs[nb][bkr][bn4]) = bv;
        }
        __syncthreads();
    }

    if (mode == 0) {
        float4 bb = *reinterpret_cast<const float4*>(&hb2[n0 + tx*4]);
        float* Or = hs + (size_t)(m0 + ty*4) * DX_ + n0 + tx*4;
        #pragma unroll
        for (int i = 0; i < 2; i++) {
            float4 lo = make_float4(acc[i][0].x+bb.x, acc[i][1].x+bb.y, acc[i][2].x+bb.z, acc[i][3].x+bb.w);
            float4 hi = make_float4(acc[i][0].y+bb.x, acc[i][1].y+bb.y, acc[i][2].y+bb.z, acc[i][3].y+bb.w);
            *reinterpret_cast<float4*>(Or + (size_t)(2*i  )*DX_) = lo;
            *reinterpret_cast<float4*>(Or + (size_t)(2*i+1)*DX_) = hi;
        }
    } else {
        float4 bb = *reinterpret_cast<const float4*>(&b1[n0 + tx*4]);
        #pragma unroll
        for (int i = 0; i < 2; i++) {
            const int r0 = m0 + ty*4 + 2*i;
            float4 p0 = *reinterpret_cast<const float4*>(&preq[(r0   /Kk_)*H_ + n0 + tx*4]);
            float4 p1 = *reinterpret_cast<const float4*>(&preq[((r0+1)/Kk_)*H_ + n0 + tx*4]);
            float4 lo = make_float4(acc[i][0].x+bb.x+p0.x, acc[i][1].x+bb.y+p0.y,
                                    acc[i][2].x+bb.z+p0.z, acc[i][3].x+bb.w+p0.w);
            float4 hi = make_float4(acc[i][0].y+bb.x+p1.x, acc[i][1].y+bb.y+p1.y,
                                    acc[i][2].y+bb.z+p1.z, acc[i][3].y+bb.w+p1.w);
            *reinterpret_cast<float4*>(&base[(size_t)(r0  )*H_ + n0 + tx*4]) = lo;
            *reinterpret_cast<float4*>(&base[(size_t)(r0+1)*H_ + n0 + tx*4]) = hi;
        }
    }
}

// ---------------------------------------------------------------------------
// att v5: 512 threads, 4 k per block, 288 blocks. Everything staged ONCE in
//   dynamic smem (~108.5KB): pre_s [64][260], hs [64][132], base, w2.
//   3 barriers total. Logits: thread=(k,m,hhalf), 32 x LDS.128, 4 chains.
//   Aggregation: thread=(k,f), 64-m loop, 4 chains.
// ---------------------------------------------------------------------------
#define ATT_SPRE  0          // 64*260 = 16640 floats
#define ATT_SHS   16640      // 64*132 = 8448
#define ATT_SBASE 25088      // 4*256  = 1024
#define ATT_SW2   26112      // 256
#define ATT_LP    26368      // 2*4*64 = 512
#define ATT_EW    26880      // 4*64   = 256
#define ATT_SINV  27136      // 4
#define ATT_SMEM_FLOATS 27140
#define ATT_SMEM_BYTES (ATT_SMEM_FLOATS*4)

__global__ void __launch_bounds__(512) att_k(
    const float* __restrict__ Cmat, const float* __restrict__ base,
    const float* __restrict__ hsm, const float* __restrict__ w2,
    const float* __restrict__ x0, float* __restrict__ out)
{
    extern __shared__ __align__(16) float zs[];
    const int b  = blockIdx.x / 9;
    const int kg = blockIdx.x % 9;
    const int bk0 = b * Kk_ + kg * 4;
    const int tid = threadIdx.x;
    const int warp = tid >> 5, lane = tid & 31;

    const float* pres = Cmat + (size_t)(b * M_) * 512;
    const float* hsb  = hsm + (size_t)(b * M_) * DX_;

    // ---- Phase 0: stage everything (one shot, high MLP) ----
    // pre_s: 64 rows x 64 float4 -> zs[ATT_SPRE + row*260 + c4]
    #pragma unroll
    for (int i = 0; i < 8; i++) {
        const int fi  = tid + i * 512;        // 0..4095
        const int row = fi >> 6;
        const int c4  = (fi & 63) * 4;
        float4 v = *reinterpret_cast<const float4*>(pres + (size_t)row * 512 + c4);
        *reinterpret_cast<float4*>(&zs[ATT_SPRE + row * 260 + c4]) = v;
    }
    // hs: 64 rows x 32 float4 -> zs[ATT_SHS + row*132 + c4]
    #pragma unroll
    for (int i = 0; i < 4; i++) {
        const int fi  = tid + i * 512;        // 0..2047
        const int row = fi >> 5;
        const int c4  = (fi & 31) * 4;
        float4 v = *reinterpret_cast<const float4*>(hsb + (size_t)row * DX_ + c4);
        *reinterpret_cast<float4*>(&zs[ATT_SHS + row * 132 + c4]) = v;
    }
    // base: 4 rows x 64 float4 (first 256 threads); w2: 64 float4 (next 64)
    if (tid < 256) {
        const int kk = tid >> 6;
        const int c4 = (tid & 63) * 4;
        float4 v = *reinterpret_cast<const float4*>(base + (size_t)(bk0 + kk) * H_ + c4);
        *reinterpret_cast<float4*>(&zs[ATT_SBASE + kk * 256 + c4]) = v;
    } else if (tid < 320) {
        const int c4 = (tid - 256) * 4;
        float4 v = *reinterpret_cast<const float4*>(w2 + c4);
        *reinterpret_cast<float4*>(&zs[ATT_SW2 + c4]) = v;
    }
    __syncthreads();

    // ---- Phase 1: logits. thread = (km, hh, mm) ----
    {
        const int km = tid >> 7;
        const int hh = (tid >> 6) & 1;
        const int mm = tid & 63;
        const float* srow = &zs[ATT_SPRE + mm * 260 + hh * 128];
        const float* bs   = &zs[ATT_SBASE + km * 256 + hh * 128];
        const float* ws   = &zs[ATT_SW2 + hh * 128];
        float a0 = 0.f, a1 = 0.f, a2 = 0.f, a3 = 0.f;
        #pragma unroll
        for (int jj = 0; jj < 32; jj++) {
            float4 v  = *reinterpret_cast<const float4*>(srow + jj * 4);
            float4 bb = *reinterpret_cast<const float4*>(bs + jj * 4);
            float4 ww = *reinterpret_cast<const float4*>(ws + jj * 4);
            a0 = fmaf(fmaxf(v.x + bb.x, 0.f), ww.x, a0);
            a1 = fmaf(fmaxf(v.y + bb.y, 0.f), ww.y, a1);
            a2 = fmaf(fmaxf(v.z + bb.z, 0.f), ww.z, a2);
            a3 = fmaf(fmaxf(v.w + bb.w, 0.f), ww.w, a3);
        }
        zs[ATT_LP + (hh * 4 + km) * 64 + mm] = (a0 + a1) + (a2 + a3);
    }
    __syncthreads();

    // ---- Phase 2: softmax (warps 0..3, one k each) ----
    if (warp < 4) {
        const int k = warp;
        float l0 = zs[ATT_LP + k * 64 + lane]      + zs[ATT_LP + (4 + k) * 64 + lane];
        float l1 = zs[ATT_LP + k * 64 + lane + 32] + zs[ATT_LP + (4 + k) * 64 + lane + 32];
        float mx = fmaxf(l0, l1);
        #pragma unroll
        for (int off = 16; off; off >>= 1)
            mx = fmaxf(mx, __shfl_xor_sync(0xffffffffu, mx, off));
        float e0 = expf(l0 - mx), e1 = expf(l1 - mx);
        float s = e0 + e1;
        #pragma unroll
        for (int off = 16; off; off >>= 1)
            s += __shfl_xor_sync(0xffffffffu, s, off);
        zs[ATT_EW + k * 64 + lane]      = e0;
        zs[ATT_EW + k * 64 + lane + 32] = e1;
        if (lane == 0) zs[ATT_SINV + k] = 1.f / s;
    }
    __syncthreads();

    // ---- Phase 3: aggregation. thread = (k, f) ----
    {
        const int k = tid >> 7;
        const int f = tid & 127;
        const float* ep = &zs[ATT_EW + k * 64];
        float a0 = 0.f, a1 = 0.f, a2 = 0.f, a3 = 0.f;
        #pragma unroll 4
        for (int m = 0; m < 64; m += 4) {
            a0 = fmaf(ep[m],     zs[ATT_SHS + (m    ) * 132 + f], a0);
            a1 = fmaf(ep[m + 1], zs[ATT_SHS + (m + 1) * 132 + f], a1);
            a2 = fmaf(ep[m + 2], zs[ATT_SHS + (m + 2) * 132 + f], a2);
            a3 = fmaf(ep[m + 3], zs[ATT_SHS + (m + 3) * 132 + f], a3);
        }
        out[(size_t)(bk0 + k) * 256 + 128 + f] = ((a0 + a1) + (a2 + a3)) * zs[ATT_SINV + k];
        // x0 copy: 4*128 = 512 elems, one per thread
        out[(size_t)(bk0 + k) * 256 + f] = x0[(size_t)(bk0 + k) * DX_ + f];
    }
}

// ---------------------------------------------------------------------------
extern "C" void kernel_launch(void* const* d_in, const int* in_sizes, int n_in,
                              void* d_out, int out_size)
{
    (void)in_sizes; (void)n_in; (void)out_size;
    const float* s2  = (const float*)d_in[0];
    const float* x0  = (const float*)d_in[1];
    const float* q   = (const float*)d_in[2];
    const float* w1  = (const float*)d_in[3];
    const float* b1  = (const float*)d_in[4];
    const float* w2  = (const float*)d_in[5];
    const float* hw1 = (const float*)d_in[7];
    const float* hb1 = (const float*)d_in[8];
    const float* hw2 = (const float*)d_in[9];
    const float* hb2 = (const float*)d_in[10];
    float* out = (float*)d_out;

    float *preq, *C, *hs, *base;
    __nv_bfloat16 *Ahi, *Alo, *Whi, *Wlo;
    cudaGetSymbolAddress((void**)&preq, g_preq);
    cudaGetSymbolAddress((void**)&C,    g_C);
    cudaGetSymbolAddress((void**)&hs,   g_hs);
    cudaGetSymbolAddress((void**)&base, g_base);
    cudaGetSymbolAddress((void**)&Ahi,  g_Ahi);
    cudaGetSymbolAddress((void**)&Alo,  g_Alo);
    cudaGetSymbolAddress((void**)&Whi,  g_Whi);
    cudaGetSymbolAddress((void**)&Wlo,  g_Wlo);

    cudaFuncSetAttribute(att_k, cudaFuncAttributeMaxDynamicSharedMemorySize,
                         ATT_SMEM_BYTES);

    // P: bf16 hi/lo split of s2 and [w_s|hw1], + preq
    prep_k<<<672, 256>>>(s2, w1, hw1, q, Ahi, Alo, Whi, Wlo, preq);
    // L1: tensor-core bf16x3 GEMM -> C (64x64 tiles, 256 blocks, BK=32)
    k1_mma<<<256, 256>>>(Ahi, Alo, Whi, Wlo, hb1, C);
    // L2: hs + base
    k2<<<136, 256>>>(C, hw2, hb2, x0, w1, b1, preq, hs, base);
    // L3: fused attention + output (512 thr, one-shot staging, 3 barriers)
    att_k<<<288, 512, ATT_SMEM_BYTES>>>(C, base, hs, w2, x0, out);
}

// round 17
// speedup vs baseline: 1.2118x; 1.0842x over previous
#include <cuda_runtime.h>
#include <cuda_bf16.h>
#include <cstdint>
#include <math.h>

typedef unsigned int u32;

#define B_  32
#define M_  64
#define Kk_ 36
#define DS_ 512
#define DX_ 128
#define DQ_ 512
#define H_  256
#define ROWS_S 2048
#define ROWS_X 1152

// Scratch (allocation-free rule: __device__ globals)
__device__ __align__(16) float g_preq[B_*H_];
__device__ __align__(16) float g_C[ROWS_S*512];      // cols 0:256 pre_s (fp32); 256:512 unused now
__device__ __align__(16) float g_hs[ROWS_S*DX_];
__device__ __align__(16) float g_base[ROWS_X*H_];
__device__ __align__(16) __nv_bfloat16 g_Ahi[ROWS_S*512];
__device__ __align__(16) __nv_bfloat16 g_Alo[ROWS_S*512];
__device__ __align__(16) __nv_bfloat16 g_Whi[512*512];   // cols 0:256 w_s, 256:512 hw1
__device__ __align__(16) __nv_bfloat16 g_Wlo[512*512];
__device__ __align__(16) __nv_bfloat16 g_H1hi[ROWS_S*H_];   // h1 = relu(s2@hw1+hb1)
__device__ __align__(16) __nv_bfloat16 g_H1lo[ROWS_S*H_];
__device__ __align__(16) __nv_bfloat16 g_X0hi[ROWS_X*DX_];
__device__ __align__(16) __nv_bfloat16 g_X0lo[ROWS_X*DX_];
__device__ __align__(16) __nv_bfloat16 g_HW2hi[H_*DX_];
__device__ __align__(16) __nv_bfloat16 g_HW2lo[H_*DX_];
__device__ __align__(16) __nv_bfloat16 g_WXhi[DX_*H_];
__device__ __align__(16) __nv_bfloat16 g_WXlo[DX_*H_];

__device__ __forceinline__ u32 smem_addr_u32(const void* zp) {
    return (u32)__cvta_generic_to_shared(zp);
}
__device__ __forceinline__ void ld_sm_x4(u32* zr, u32 zaddr) {
    asm volatile("ldmatrix.sync.aligned.m8n8.x4.shared.b16 {%0,%1,%2,%3}, [%4];"
        : "=r"(zr[0]), "=r"(zr[1]), "=r"(zr[2]), "=r"(zr[3]) : "r"(zaddr));
}
__device__ __forceinline__ void ld_sm_x4_t(u32* zr, u32 zaddr) {
    asm volatile("ldmatrix.sync.aligned.m8n8.x4.trans.shared.b16 {%0,%1,%2,%3}, [%4];"
        : "=r"(zr[0]), "=r"(zr[1]), "=r"(zr[2]), "=r"(zr[3]) : "r"(zaddr));
}
__device__ __forceinline__ void mma16816(float* zc, const u32* za, u32 zb0, u32 zb1) {
    asm volatile("mma.sync.aligned.m16n8k16.row.col.f32.bf16.bf16.f32 "
        "{%0,%1,%2,%3},{%4,%5,%6,%7},{%8,%9},{%0,%1,%2,%3};"
        : "+f"(zc[0]), "+f"(zc[1]), "+f"(zc[2]), "+f"(zc[3])
        : "r"(za[0]), "r"(za[1]), "r"(za[2]), "r"(za[3]), "r"(zb0), "r"(zb1));
}
// split float2 into packed bf16x2 hi and lo words
__device__ __forceinline__ void split_bf2(float2 zv, u32& zhw, u32& zlw) {
    __nv_bfloat162 zh;
    zh.x = __float2bfloat16(zv.x);
    zh.y = __float2bfloat16(zv.y);
    __nv_bfloat162 zl;
    zl.x = __float2bfloat16(zv.x - __bfloat162float(zh.x));
    zl.y = __float2bfloat16(zv.y - __bfloat162float(zh.y));
    zhw = *reinterpret_cast<u32*>(&zh);
    zlw = *reinterpret_cast<u32*>(&zl);
}

// ---------------------------------------------------------------------------
// prep: bx<512  : split s2 -> (Ahi, Alo)
//       512..639: split [w_s|hw1] -> (Whi,Wlo)
//       640..711: split x0
//       712..727: split hw2
//       728..743: split w_x (w1 rows 512..639)
//       bx>=744 : preq[b] = q[b] @ w_q
// ---------------------------------------------------------------------------
__global__ void __launch_bounds__(256) prep_k(
    const float* __restrict__ s2, const float* __restrict__ w1,
    const float* __restrict__ hw1, const float* __restrict__ q,
    const float* __restrict__ x0, const float* __restrict__ hw2,
    __nv_bfloat16* __restrict__ Ahi, __nv_bfloat16* __restrict__ Alo,
    __nv_bfloat16* __restrict__ Whi, __nv_bfloat16* __restrict__ Wlo,
    __nv_bfloat16* __restrict__ X0hi, __nv_bfloat16* __restrict__ X0lo,
    __nv_bfloat16* __restrict__ HW2hi, __nv_bfloat16* __restrict__ HW2lo,
    __nv_bfloat16* __restrict__ WXhi, __nv_bfloat16* __restrict__ WXlo,
    float* __restrict__ preq)
{
    const int ztid = threadIdx.x;
    const int zbx  = blockIdx.x;

    const float* zsrc = 0;
    __nv_bfloat16* zdhi = 0;
    __nv_bfloat16* zdlo = 0;
    size_t zoff = 0;
    bool zdo = false;

    if (zbx < 512) {
        zoff = ((size_t)zbx * 256 + ztid) * 8;
        zsrc = s2 + zoff; zdhi = Ahi; zdlo = Alo; zdo = true;
    } else if (zbx < 640) {
        zoff = ((size_t)(zbx - 512) * 256 + ztid) * 8;
        const int zk = (int)(zoff >> 9);
        const int zn = (int)(zoff & 511);
        zsrc = (zn < 256) ? (w1 + (size_t)zk*256 + zn)
                          : (hw1 + (size_t)zk*256 + (zn - 256));
        zdhi = Whi; zdlo = Wlo; zdo = true;
    } else if (zbx < 712) {
        zoff = ((size_t)(zbx - 640) * 256 + ztid) * 8;   // < 147456
        zsrc = x0 + zoff; zdhi = X0hi; zdlo = X0lo; zdo = true;
    } else if (zbx < 728) {
        zoff = ((size_t)(zbx - 712) * 256 + ztid) * 8;   // < 32768
        zsrc = hw2 + zoff; zdhi = HW2hi; zdlo = HW2lo; zdo = true;
    } else if (zbx < 744) {
        zoff = ((size_t)(zbx - 728) * 256 + ztid) * 8;   // < 32768
        zsrc = w1 + (size_t)DS_*H_ + zoff; zdhi = WXhi; zdlo = WXlo; zdo = true;
    }

    if (zdo) {
        float4 zva = *reinterpret_cast<const float4*>(zsrc);
        float4 zvb = *reinterpret_cast<const float4*>(zsrc + 4);
        float zv[8] = {zva.x,zva.y,zva.z,zva.w,zvb.x,zvb.y,zvb.z,zvb.w};
        __nv_bfloat16 zhi[8];
        __nv_bfloat16 zlo[8];
        #pragma unroll
        for (int zi = 0; zi < 8; zi++) {
            zhi[zi] = __float2bfloat16(zv[zi]);
            zlo[zi] = __float2bfloat16(zv[zi] - __bfloat162float(zhi[zi]));
        }
        *reinterpret_cast<uint4*>(zdhi + zoff) = *reinterpret_cast<uint4*>(zhi);
        *reinterpret_cast<uint4*>(zdlo + zoff) = *reinterpret_cast<uint4*>(zlo);
        return;
    }

    __shared__ float zqs[DQ_];
    const int zb = zbx - 744;
    for (int zd = ztid; zd < DQ_; zd += 256) zqs[zd] = q[zb*DQ_ + zd];
    __syncthreads();
    const float* zwq = w1 + (size_t)(DS_ + DX_) * H_ + ztid;
    float zacc0 = 0.f;
    float zacc1 = 0.f;
    #pragma unroll 8
    for (int zd = 0; zd < DQ_; zd += 2) {
        zacc0 = fmaf(zqs[zd],   zwq[(size_t)zd*H_],     zacc0);
        zacc1 = fmaf(zqs[zd+1], zwq[(size_t)(zd+1)*H_], zacc1);
    }
    preq[zb*H_ + ztid] = zacc0 + zacc1;
}

// ---------------------------------------------------------------------------
// k1_mma: 64x64 tile, BK=32, 256 blocks, 8 warps (2m x 4n), bf16x3.
//   cols<256: C fp32 (pre_s). cols>=256: h1=relu(..+hb1) -> bf16 hi/lo H1.
// ---------------------------------------------------------------------------
__global__ void __launch_bounds__(256) k1_mma(
    const __nv_bfloat16* __restrict__ Ahi, const __nv_bfloat16* __restrict__ Alo,
    const __nv_bfloat16* __restrict__ Whi, const __nv_bfloat16* __restrict__ Wlo,
    const float* __restrict__ hb1, float* __restrict__ C,
    __nv_bfloat16* __restrict__ H1hi, __nv_bfloat16* __restrict__ H1lo)
{
    __shared__ __align__(16) __nv_bfloat16 zSAhi[2][64][40];
    __shared__ __align__(16) __nv_bfloat16 zSAlo[2][64][40];
    __shared__ __align__(16) __nv_bfloat16 zSBhi[2][32][72];
    __shared__ __align__(16) __nv_bfloat16 zSBlo[2][32][72];

    const int ztid  = threadIdx.x;
    const int zbx   = blockIdx.x;
    const int zbm   = zbx >> 3;
    const int zbn   = zbx & 7;
    const int zm0   = zbm * 64;
    const int zn0   = zbn * 64;
    const int zwarp = ztid >> 5;
    const int zlane = ztid & 31;
    const int zwm   = zwarp & 1;
    const int zwn   = zwarp >> 1;

    const int zArow = ztid >> 2;
    const int zAseg = (ztid & 3) * 8;
    const __nv_bfloat16* zgAhi = Ahi + (size_t)(zm0 + zArow) * 512 + zAseg;
    const __nv_bfloat16* zgAlo = Alo + (size_t)(zm0 + zArow) * 512 + zAseg;
    const int zBrow = ztid >> 3;
    const int zBcol = (ztid & 7) * 8;
    const __nv_bfloat16* zgBhi = Whi + (size_t)zBrow * 512 + zn0 + zBcol;
    const __nv_bfloat16* zgBlo = Wlo + (size_t)zBrow * 512 + zn0 + zBcol;

    float zacc[2][2][4];
    #pragma unroll
    for (int zf = 0; zf < 2; zf++) {
        #pragma unroll
        for (int zg = 0; zg < 2; zg++) {
            #pragma unroll
            for (int ze = 0; ze < 4; ze++) zacc[zf][zg][ze] = 0.f;
        }
    }

    u32 zAdrAhi[2];
    u32 zAdrAlo[2];
    u32 zAdrBhi;
    u32 zAdrBlo;
    {
        const int zquad = zlane >> 3;
        const int zr8   = zlane & 7;
        #pragma unroll
        for (int zf = 0; zf < 2; zf++) {
            const int zrr = zwm*32 + zf*16 + (zquad & 1)*8 + zr8;
            const int zcc = (zquad >> 1) * 8;
            zAdrAhi[zf] = smem_addr_u32(&zSAhi[0][zrr][zcc]);
            zAdrAlo[zf] = smem_addr_u32(&zSAlo[0][zrr][zcc]);
        }
        const int zkr = (zquad & 1)*8 + zr8;
        const int znc = zwn*16 + (zquad >> 1)*8;
        zAdrBhi = smem_addr_u32(&zSBhi[0][zkr][znc]);
        zAdrBlo = smem_addr_u32(&zSBlo[0][zkr][znc]);
    }
    const u32 zBufA = (u32)(64*40*2);
    const u32 zBufB = (u32)(32*72*2);
    const u32 zKkA  = 32;
    const u32 zKkB  = (u32)(16*72*2);

    uint4 zPfAhi = *reinterpret_cast<const uint4*>(zgAhi);
    uint4 zPfAlo = *reinterpret_cast<const uint4*>(zgAlo);
    uint4 zPfBhi = *reinterpret_cast<const uint4*>(zgBhi);
    uint4 zPfBlo = *reinterpret_cast<const uint4*>(zgBlo);
    *reinterpret_cast<uint4*>(&zSAhi[0][zArow][zAseg]) = zPfAhi;
    *reinterpret_cast<uint4*>(&zSAlo[0][zArow][zAseg]) = zPfAlo;
    *reinterpret_cast<uint4*>(&zSBhi[0][zBrow][zBcol]) = zPfBhi;
    *reinterpret_cast<uint4*>(&zSBlo[0][zBrow][zBcol]) = zPfBlo;
    __syncthreads();

    #pragma unroll 1
    for (int zkt = 0; zkt < 16; zkt++) {
        const int zbuf = zkt & 1;
        if (zkt < 15) {
            zPfAhi = *reinterpret_cast<const uint4*>(zgAhi + (zkt+1)*32);
            zPfAlo = *reinterpret_cast<const uint4*>(zgAlo + (zkt+1)*32);
            zPfBhi = *reinterpret_cast<const uint4*>(zgBhi + (size_t)(zkt+1)*32*512);
            zPfBlo = *reinterpret_cast<const uint4*>(zgBlo + (size_t)(zkt+1)*32*512);
        }
        #pragma unroll
        for (int zkk = 0; zkk < 2; zkk++) {
            u32 zFAhi[2][4];
            u32 zFAlo[2][4];
            u32 zFBhi[4];
            u32 zFBlo[4];
            #pragma unroll
            for (int zf = 0; zf < 2; zf++) {
                ld_sm_x4(zFAhi[zf], zAdrAhi[zf] + zbuf*zBufA + zkk*zKkA);
                ld_sm_x4(zFAlo[zf], zAdrAlo[zf] + zbuf*zBufA + zkk*zKkA);
            }
            ld_sm_x4_t(zFBhi, zAdrBhi + zbuf*zBufB + zkk*zKkB);
            ld_sm_x4_t(zFBlo, zAdrBlo + zbuf*zBufB + zkk*zKkB);
            #pragma unroll
            for (int zf = 0; zf < 2; zf++) {
                #pragma unroll
                for (int zg = 0; zg < 2; zg++) {
                    const int zs = zg * 2;
                    mma16816(zacc[zf][zg], zFAhi[zf], zFBhi[zs], zFBhi[zs+1]);
                    mma16816(zacc[zf][zg], zFAhi[zf], zFBlo[zs], zFBlo[zs+1]);
                    mma16816(zacc[zf][zg], zFAlo[zf], zFBhi[zs], zFBhi[zs+1]);
                }
            }
        }
        if (zkt < 15) {
            const int znb = zbuf ^ 1;
            *reinterpret_cast<uint4*>(&zSAhi[znb][zArow][zAseg]) = zPfAhi;
            *reinterpret_cast<uint4*>(&zSAlo[znb][zArow][zAseg]) = zPfAlo;
            *reinterpret_cast<uint4*>(&zSBhi[znb][zBrow][zBcol]) = zPfBhi;
            *reinterpret_cast<uint4*>(&zSBlo[znb][zBrow][zBcol]) = zPfBlo;
        }
        __syncthreads();
    }

    const bool zRelu = (zn0 >= 256);
    #pragma unroll
    for (int zf = 0; zf < 2; zf++) {
        #pragma unroll
        for (int zg = 0; zg < 2; zg++) {
            const int zrow = zm0 + zwm*32 + zf*16 + (zlane >> 2);
            const int zcol = zn0 + zwn*16 + zg*8 + (zlane & 3)*2;
            float2 zv0 = make_float2(zacc[zf][zg][0], zacc[zf][zg][1]);
            float2 zv1 = make_float2(zacc[zf][zg][2], zacc[zf][zg][3]);
            if (zRelu) {
                const int zc = zcol - 256;
                float2 zbb = *reinterpret_cast<const float2*>(&hb1[zc]);
                zv0.x = fmaxf(zv0.x + zbb.x, 0.f); zv0.y = fmaxf(zv0.y + zbb.y, 0.f);
                zv1.x = fmaxf(zv1.x + zbb.x, 0.f); zv1.y = fmaxf(zv1.y + zbb.y, 0.f);
                u32 zh0, zl0, zh1, zl1;
                split_bf2(zv0, zh0, zl0);
                split_bf2(zv1, zh1, zl1);
                *reinterpret_cast<u32*>(&H1hi[(size_t)zrow * H_ + zc])       = zh0;
                *reinterpret_cast<u32*>(&H1lo[(size_t)zrow * H_ + zc])       = zl0;
                *reinterpret_cast<u32*>(&H1hi[(size_t)(zrow + 8) * H_ + zc]) = zh1;
                *reinterpret_cast<u32*>(&H1lo[(size_t)(zrow + 8) * H_ + zc]) = zl1;
            } else {
                *reinterpret_cast<float2*>(&C[(size_t)zrow * 512 + zcol])       = zv0;
                *reinterpret_cast<float2*>(&C[(size_t)(zrow + 8) * 512 + zcol]) = zv1;
            }
        }
    }
}

// ---------------------------------------------------------------------------
// k2_mma: both small GEMMs on tensor cores (bf16x3), 136 blocks.
//   bx<64 : hs[2048,128] = H1 @ hw2 + hb2        (K=256, 8 iters)
//   bx>=64: base[1152,256] = x0 @ w_x + b1+preq  (K=128, 4 iters)
// ---------------------------------------------------------------------------
__global__ void __launch_bounds__(256) k2_mma(
    const __nv_bfloat16* __restrict__ H1hi, const __nv_bfloat16* __restrict__ H1lo,
    const __nv_bfloat16* __restrict__ HW2hi, const __nv_bfloat16* __restrict__ HW2lo,
    const __nv_bfloat16* __restrict__ X0hi, const __nv_bfloat16* __restrict__ X0lo,
    const __nv_bfloat16* __restrict__ WXhi, const __nv_bfloat16* __restrict__ WXlo,
    const float* __restrict__ hb2, const float* __restrict__ b1,
    const float* __restrict__ preq,
    float* __restrict__ hs, float* __restrict__ basep)
{
    __shared__ __align__(16) __nv_bfloat16 zSAhi[2][64][40];
    __shared__ __align__(16) __nv_bfloat16 zSAlo[2][64][40];
    __shared__ __align__(16) __nv_bfloat16 zSBhi[2][32][72];
    __shared__ __align__(16) __nv_bfloat16 zSBlo[2][32][72];

    const int ztid  = threadIdx.x;
    const int zbx   = blockIdx.x;
    const int zwarp = ztid >> 5;
    const int zlane = ztid & 31;
    const int zwm   = zwarp & 1;
    const int zwn   = zwarp >> 1;

    const __nv_bfloat16* zAh;
    const __nv_bfloat16* zAl;
    const __nv_bfloat16* zBh;
    const __nv_bfloat16* zBl;
    int zlda, zldb, zm0, zn0, znkt, zmode;
    if (zbx < 64) {
        zmode = 0;
        zm0 = (zbx >> 1) * 64;
        zn0 = (zbx & 1) * 64;
        zAh = H1hi; zAl = H1lo; zlda = 256;
        zBh = HW2hi; zBl = HW2lo; zldb = 128;
        znkt = 8;
    } else {
        zmode = 1;
        const int zbb = zbx - 64;
        zm0 = (zbb >> 2) * 64;
        zn0 = (zbb & 3) * 64;
        zAh = X0hi; zAl = X0lo; zlda = 128;
        zBh = WXhi; zBl = WXlo; zldb = 256;
        znkt = 4;
    }

    const int zArow = ztid >> 2;
    const int zAseg = (ztid & 3) * 8;
    const __nv_bfloat16* zgAhi = zAh + (size_t)(zm0 + zArow) * zlda + zAseg;
    const __nv_bfloat16* zgAlo = zAl + (size_t)(zm0 + zArow) * zlda + zAseg;
    const int zBrow = ztid >> 3;
    const int zBcol = (ztid & 7) * 8;
    const __nv_bfloat16* zgBhi = zBh + (size_t)zBrow * zldb + zn0 + zBcol;
    const __nv_bfloat16* zgBlo = zBl + (size_t)zBrow * zldb + zn0 + zBcol;

    float zacc[2][2][4];
    #pragma unroll
    for (int zf = 0; zf < 2; zf++) {
        #pragma unroll
        for (int zg = 0; zg < 2; zg++) {
            #pragma unroll
            for (int ze = 0; ze < 4; ze++) zacc[zf][zg][ze] = 0.f;
        }
    }

    u32 zAdrAhi[2];
    u32 zAdrAlo[2];
    u32 zAdrBhi;
    u32 zAdrBlo;
    {
        const int zquad = zlane >> 3;
        const int zr8   = zlane & 7;
        #pragma unroll
        for (int zf = 0; zf < 2; zf++) {
            const int zrr = zwm*32 + zf*16 + (zquad & 1)*8 + zr8;
            const int zcc = (zquad >> 1) * 8;
            zAdrAhi[zf] = smem_addr_u32(&zSAhi[0][zrr][zcc]);
            zAdrAlo[zf] = smem_addr_u32(&zSAlo[0][zrr][zcc]);
        }
        const int zkr = (zquad & 1)*8 + zr8;
        const int znc = zwn*16 + (zquad >> 1)*8;
        zAdrBhi = smem_addr_u32(&zSBhi[0][zkr][znc]);
        zAdrBlo = smem_addr_u32(&zSBlo[0][zkr][znc]);
    }
    const u32 zBufA = (u32)(64*40*2);
    const u32 zBufB = (u32)(32*72*2);
    const u32 zKkA  = 32;
    const u32 zKkB  = (u32)(16*72*2);

    uint4 zPfAhi = *reinterpret_cast<const uint4*>(zgAhi);
    uint4 zPfAlo = *reinterpret_cast<const uint4*>(zgAlo);
    uint4 zPfBhi = *reinterpret_cast<const uint4*>(zgBhi);
    uint4 zPfBlo = *reinterpret_cast<const uint4*>(zgBlo);
    *reinterpret_cast<uint4*>(&zSAhi[0][zArow][zAseg]) = zPfAhi;
    *reinterpret_cast<uint4*>(&zSAlo[0][zArow][zAseg]) = zPfAlo;
    *reinterpret_cast<uint4*>(&zSBhi[0][zBrow][zBcol]) = zPfBhi;
    *reinterpret_cast<uint4*>(&zSBlo[0][zBrow][zBcol]) = zPfBlo;
    __syncthreads();

    #pragma unroll 1
    for (int zkt = 0; zkt < znkt; zkt++) {
        const int zbuf = zkt & 1;
        if (zkt + 1 < znkt) {
            zPfAhi = *reinterpret_cast<const uint4*>(zgAhi + (zkt+1)*32);
            zPfAlo = *reinterpret_cast<const uint4*>(zgAlo + (zkt+1)*32);
            zPfBhi = *reinterpret_cast<const uint4*>(zgBhi + (size_t)(zkt+1)*32*zldb);
            zPfBlo = *reinterpret_cast<const uint4*>(zgBlo + (size_t)(zkt+1)*32*zldb);
        }
        #pragma unroll
        for (int zkk = 0; zkk < 2; zkk++) {
            u32 zFAhi[2][4];
            u32 zFAlo[2][4];
            u32 zFBhi[4];
            u32 zFBlo[4];
            #pragma unroll
            for (int zf = 0; zf < 2; zf++) {
                ld_sm_x4(zFAhi[zf], zAdrAhi[zf] + zbuf*zBufA + zkk*zKkA);
                ld_sm_x4(zFAlo[zf], zAdrAlo[zf] + zbuf*zBufA + zkk*zKkA);
            }
            ld_sm_x4_t(zFBhi, zAdrBhi + zbuf*zBufB + zkk*zKkB);
            ld_sm_x4_t(zFBlo, zAdrBlo + zbuf*zBufB + zkk*zKkB);
            #pragma unroll
            for (int zf = 0; zf < 2; zf++) {
                #pragma unroll
                for (int zg = 0; zg < 2; zg++) {
                    const int zs = zg * 2;
                    mma16816(zacc[zf][zg], zFAhi[zf], zFBhi[zs], zFBhi[zs+1]);
                    mma16816(zacc[zf][zg], zFAhi[zf], zFBlo[zs], zFBlo[zs+1]);
                    mma16816(zacc[zf][zg], zFAlo[zf], zFBhi[zs], zFBhi[zs+1]);
                }
            }
        }
        if (zkt + 1 < znkt) {
            const int znb = zbuf ^ 1;
            *reinterpret_cast<uint4*>(&zSAhi[znb][zArow][zAseg]) = zPfAhi;
            *reinterpret_cast<uint4*>(&zSAlo[znb][zArow][zAseg]) = zPfAlo;
            *reinterpret_cast<uint4*>(&zSBhi[znb][zBrow][zBcol]) = zPfBhi;
            *reinterpret_cast<uint4*>(&zSBlo[znb][zBrow][zBcol]) = zPfBlo;
        }
        __syncthreads();
    }

    #pragma unroll
    for (int zf = 0; zf < 2; zf++) {
        #pragma unroll
        for (int zg = 0; zg < 2; zg++) {
            const int zrow = zm0 + zwm*32 + zf*16 + (zlane >> 2);
            const int zcol = zn0 + zwn*16 + zg*8 + (zlane & 3)*2;
            float2 zv0 = make_float2(zacc[zf][zg][0], zacc[zf][zg][1]);
            float2 zv1 = make_float2(zacc[zf][zg][2], zacc[zf][zg][3]);
            if (zmode == 0) {
                float2 zbb = *reinterpret_cast<const float2*>(&hb2[zcol]);
                zv0.x += zbb.x; zv0.y += zbb.y;
                zv1.x += zbb.x; zv1.y += zbb.y;
                *reinterpret_cast<float2*>(&hs[(size_t)zrow * DX_ + zcol])       = zv0;
                *reinterpret_cast<float2*>(&hs[(size_t)(zrow + 8) * DX_ + zcol]) = zv1;
            } else {
                float2 zbb = *reinterpret_cast<const float2*>(&b1[zcol]);
                float2 zp0 = *reinterpret_cast<const float2*>(&preq[(zrow / Kk_) * H_ + zcol]);
                float2 zp1 = *reinterpret_cast<const float2*>(&preq[((zrow + 8) / Kk_) * H_ + zcol]);
                zv0.x += zbb.x + zp0.x; zv0.y += zbb.y + zp0.y;
                zv1.x += zbb.x + zp1.x; zv1.y += zbb.y + zp1.y;
                *reinterpret_cast<float2*>(&basep[(size_t)zrow * H_ + zcol])       = zv0;
                *reinterpret_cast<float2*>(&basep[(size_t)(zrow + 8) * H_ + zcol]) = zv1;
            }
        }
    }
}

// ---------------------------------------------------------------------------
// att v5: 512 threads, 4 k per block, 288 blocks, one-shot smem staging.
// ---------------------------------------------------------------------------
#define ATT_SPRE  0
#define ATT_SHS   16640
#define ATT_SBASE 25088
#define ATT_SW2   26112
#define ATT_LP    26368
#define ATT_EW    26880
#define ATT_SINV  27136
#define ATT_SMEM_FLOATS 27140
#define ATT_SMEM_BYTES (ATT_SMEM_FLOATS*4)

__global__ void __launch_bounds__(512) att_k(
    const float* __restrict__ Cmat, const float* __restrict__ base,
    const float* __restrict__ hsm, const float* __restrict__ w2,
    const float* __restrict__ x0, float* __restrict__ out)
{
    extern __shared__ __align__(16) float zs[];
    const int b  = blockIdx.x / 9;
    const int kg = blockIdx.x % 9;
    const int bk0 = b * Kk_ + kg * 4;
    const int tid = threadIdx.x;
    const int warp = tid >> 5, lane = tid & 31;

    const float* pres = Cmat + (size_t)(b * M_) * 512;
    const float* hsb  = hsm + (size_t)(b * M_) * DX_;

    #pragma unroll
    for (int i = 0; i < 8; i++) {
        const int fi  = tid + i * 512;
        const int row = fi >> 6;
        const int c4  = (fi & 63) * 4;
        float4 v = *reinterpret_cast<const float4*>(pres + (size_t)row * 512 + c4);
        *reinterpret_cast<float4*>(&zs[ATT_SPRE + row * 260 + c4]) = v;
    }
    #pragma unroll
    for (int i = 0; i < 4; i++) {
        const int fi  = tid + i * 512;
        const int row = fi >> 5;
        const int c4  = (fi & 31) * 4;
        float4 v = *reinterpret_cast<const float4*>(hsb + (size_t)row * DX_ + c4);
        *reinterpret_cast<float4*>(&zs[ATT_SHS + row * 132 + c4]) = v;
    }
    if (tid < 256) {
        const int kk = tid >> 6;
        const int c4 = (tid & 63) * 4;
        float4 v = *reinterpret_cast<const float4*>(base + (size_t)(bk0 + kk) * H_ + c4);
        *reinterpret_cast<float4*>(&zs[ATT_SBASE + kk * 256 + c4]) = v;
    } else if (tid < 320) {
        const int c4 = (tid - 256) * 4;
        float4 v = *reinterpret_cast<const float4*>(w2 + c4);
        *reinterpret_cast<float4*>(&zs[ATT_SW2 + c4]) = v;
    }
    __syncthreads();

    {
        const int km = tid >> 7;
        const int hh = (tid >> 6) & 1;
        const int mm = tid & 63;
        const float* srow = &zs[ATT_SPRE + mm * 260 + hh * 128];
        const float* bs   = &zs[ATT_SBASE + km * 256 + hh * 128];
        const float* ws   = &zs[ATT_SW2 + hh * 128];
        float a0 = 0.f, a1 = 0.f, a2 = 0.f, a3 = 0.f;
        #pragma unroll
        for (int jj = 0; jj < 32; jj++) {
            float4 v  = *reinterpret_cast<const float4*>(srow + jj * 4);
            float4 bb = *reinterpret_cast<const float4*>(bs + jj * 4);
            float4 ww = *reinterpret_cast<const float4*>(ws + jj * 4);
            a0 = fmaf(fmaxf(v.x + bb.x, 0.f), ww.x, a0);
            a1 = fmaf(fmaxf(v.y + bb.y, 0.f), ww.y, a1);
            a2 = fmaf(fmaxf(v.z + bb.z, 0.f), ww.z, a2);
            a3 = fmaf(fmaxf(v.w + bb.w, 0.f), ww.w, a3);
        }
        zs[ATT_LP + (hh * 4 + km) * 64 + mm] = (a0 + a1) + (a2 + a3);
    }
    __syncthreads();

    if (warp < 4) {
        const int k = warp;
        float l0 = zs[ATT_LP + k * 64 + lane]      + zs[ATT_LP + (4 + k) * 64 + lane];
        float l1 = zs[ATT_LP + k * 64 + lane + 32] + zs[ATT_LP + (4 + k) * 64 + lane + 32];
        float mx = fmaxf(l0, l1);
        #pragma unroll
        for (int off = 16; off; off >>= 1)
            mx = fmaxf(mx, __shfl_xor_sync(0xffffffffu, mx, off));
        float e0 = expf(l0 - mx), e1 = expf(l1 - mx);
        float s = e0 + e1;
        #pragma unroll
        for (int off = 16; off; off >>= 1)
            s += __shfl_xor_sync(0xffffffffu, s, off);
        zs[ATT_EW + k * 64 + lane]      = e0;
        zs[ATT_EW + k * 64 + lane + 32] = e1;
        if (lane == 0) zs[ATT_SINV + k] = 1.f / s;
    }
    __syncthreads();

    {
        const int k = tid >> 7;
        const int f = tid & 127;
        const float* ep = &zs[ATT_EW + k * 64];
        float a0 = 0.f, a1 = 0.f, a2 = 0.f, a3 = 0.f;
        #pragma unroll 4
        for (int m = 0; m < 64; m += 4) {
            a0 = fmaf(ep[m],     zs[ATT_SHS + (m    ) * 132 + f], a0);
            a1 = fmaf(ep[m + 1], zs[ATT_SHS + (m + 1) * 132 + f], a1);
            a2 = fmaf(ep[m + 2], zs[ATT_SHS + (m + 2) * 132 + f], a2);
            a3 = fmaf(ep[m + 3], zs[ATT_SHS + (m + 3) * 132 + f], a3);
        }
        out[(size_t)(bk0 + k) * 256 + 128 + f] = ((a0 + a1) + (a2 + a3)) * zs[ATT_SINV + k];
        out[(size_t)(bk0 + k) * 256 + f] = x0[(size_t)(bk0 + k) * DX_ + f];
    }
}

// ---------------------------------------------------------------------------
extern "C" void kernel_launch(void* const* d_in, const int* in_sizes, int n_in,
                              void* d_out, int out_size)
{
    (void)in_sizes; (void)n_in; (void)out_size;
    const float* s2  = (const float*)d_in[0];
    const float* x0  = (const float*)d_in[1];
    const float* q   = (const float*)d_in[2];
    const float* w1  = (const float*)d_in[3];
    const float* b1  = (const float*)d_in[4];
    const float* w2  = (const float*)d_in[5];
    const float* hw1 = (const float*)d_in[7];
    const float* hb1 = (const float*)d_in[8];
    const float* hw2 = (const float*)d_in[9];
    const float* hb2 = (const float*)d_in[10];
    float* out = (float*)d_out;

    float *preq, *C, *hs, *base;
    __nv_bfloat16 *Ahi, *Alo, *Whi, *Wlo, *H1hi, *H1lo, *X0hi, *X0lo;
    __nv_bfloat16 *HW2hi, *HW2lo, *WXhi, *WXlo;
    cudaGetSymbolAddress((void**)&preq,  g_preq);
    cudaGetSymbolAddress((void**)&C,     g_C);
    cudaGetSymbolAddress((void**)&hs,    g_hs);
    cudaGetSymbolAddress((void**)&base,  g_base);
    cudaGetSymbolAddress((void**)&Ahi,   g_Ahi);
    cudaGetSymbolAddress((void**)&Alo,   g_Alo);
    cudaGetSymbolAddress((void**)&Whi,   g_Whi);
    cudaGetSymbolAddress((void**)&Wlo,   g_Wlo);
    cudaGetSymbolAddress((void**)&H1hi,  g_H1hi);
    cudaGetSymbolAddress((void**)&H1lo,  g_H1lo);
    cudaGetSymbolAddress((void**)&X0hi,  g_X0hi);
    cudaGetSymbolAddress((void**)&X0lo,  g_X0lo);
    cudaGetSymbolAddress((void**)&HW2hi, g_HW2hi);
    cudaGetSymbolAddress((void**)&HW2lo, g_HW2lo);
    cudaGetSymbolAddress((void**)&WXhi,  g_WXhi);
    cudaGetSymbolAddress((void**)&WXlo,  g_WXlo);

    cudaFuncSetAttribute(att_k, cudaFuncAttributeMaxDynamicSharedMemorySize,
                         ATT_SMEM_BYTES);

    // P: bf16 hi/lo splits (s2, W, x0, hw2, w_x) + preq
    prep_k<<<776, 256>>>(s2, w1, hw1, q, x0, hw2,
                         Ahi, Alo, Whi, Wlo, X0hi, X0lo,
                         HW2hi, HW2lo, WXhi, WXlo, preq);
    // L1: big GEMM -> pre_s (fp32) + h1 (bf16 hi/lo)
    k1_mma<<<256, 256>>>(Ahi, Alo, Whi, Wlo, hb1, C, H1hi, H1lo);
    // L2: hs + base, both on tensor cores
    k2_mma<<<136, 256>>>(H1hi, H1lo, HW2hi, HW2lo, X0hi, X0lo, WXhi, WXlo,
                         hb2, b1, preq, hs, base);
    // L3: fused attention + output
    att_k<<<288, 512, ATT_SMEM_BYTES>>>(C, base, hs, w2, x0, out);
}